// round 11
// baseline (speedup 1.0000x reference)
#include <cuda_runtime.h>
#include <cuda_bf16.h>
#include <cstdint>
#include <math.h>

// ---------------------------------------------------------------------------
// Problem constants
// ---------------------------------------------------------------------------
#define BB   32
#define TT   256
#define DD   512
#define HH   512
#define AA   128
#define MROWS 8192      // B*T
#define NG    2048      // 4H
#define NAG   512       // 4A

typedef __nv_bfloat16 bf16;

// ---------------------------------------------------------------------------
// Static device workspace
// ---------------------------------------------------------------------------
__device__ float g_xg [2][MROWS * NG];    // per dir: x@Wx + b. row = b*T+t
__device__ float g_axg[2][MROWS * NAG];   // per dir: x@aWx + ab. row = b*T+t
__device__ float g_ahst[2][2][BB * AA];   // double-buffered adaptive hidden state
__device__ bf16  g_hsth[2][2][BB * HH];   // double-buffered main hidden (hi)
__device__ bf16  g_hstl[2][2][BB * HH];   // double-buffered main hidden (lo)

// Epoch flags: one 128B-padded slot per CTA
__device__ unsigned g_mflag[2][64][32];   // mscan CTAs
__device__ unsigned g_aflag[2][32][32];   // ascan CTAs

// bf16 hi/lo splits
__device__ bf16 g_Xhi [MROWS * DD],  g_Xlo [MROWS * DD];
__device__ bf16 g_Wxhi[2][DD * NG],  g_Wxlo[2][DD * NG];
__device__ bf16 g_aWxhi[2][DD * NAG], g_aWxlo[2][DD * NAG];

// t-major adaptive hidden stream for mscan consumption: [dir][t][b*128+c]
__device__ bf16 g_ahT_hi[2][TT][BB * AA];
__device__ bf16 g_ahT_lo[2][TT][BB * AA];

__device__ __forceinline__ float sigm(float x) { return 1.f / (1.f + expf(-x)); }

// --- release/acquire primitives -------------------------------------------
__device__ __forceinline__ void st_release_gpu(unsigned* p, unsigned v) {
    asm volatile("st.release.gpu.global.u32 [%0], %1;" :: "l"(p), "r"(v));
}
__device__ __forceinline__ unsigned ld_acquire_gpu(const unsigned* p) {
    unsigned v;
    asm volatile("ld.acquire.gpu.global.u32 %0, [%1];" : "=r"(v) : "l"(p));
    return v;
}
__device__ __forceinline__ void poll_flag(const unsigned* p, unsigned tgt) {
    int s = 0;
    while (ld_acquire_gpu(p) < tgt) {
        if (++s > 16) __nanosleep(40);
    }
}

// --- cp.async (16B, L2-direct) --------------------------------------------
__device__ __forceinline__ void cp16(uint32_t dst, const void* src) {
    asm volatile("cp.async.cg.shared.global [%0], [%1], 16;" :: "r"(dst), "l"(src));
}
__device__ __forceinline__ void cp_commit() {
    asm volatile("cp.async.commit_group;");
}
__device__ __forceinline__ void cp_wait0() {
    asm volatile("cp.async.wait_group 0;" ::: "memory");
}
__device__ __forceinline__ void cp_wait1() {
    asm volatile("cp.async.wait_group 1;" ::: "memory");
}

// ---------------------------------------------------------------------------
// mma.sync helpers (bf16, m16n8k16, fp32 accumulate)
// ---------------------------------------------------------------------------
__device__ __forceinline__ uint32_t cvta_s(const void* p) {
    return (uint32_t)__cvta_generic_to_shared(p);
}
__device__ __forceinline__ void ldsm_x4(uint32_t& r0, uint32_t& r1, uint32_t& r2, uint32_t& r3, uint32_t a) {
    asm volatile("ldmatrix.sync.aligned.m8n8.x4.shared.b16 {%0,%1,%2,%3}, [%4];"
                 : "=r"(r0), "=r"(r1), "=r"(r2), "=r"(r3) : "r"(a));
}
__device__ __forceinline__ void ldsm_x2(uint32_t& r0, uint32_t& r1, uint32_t a) {
    asm volatile("ldmatrix.sync.aligned.m8n8.x2.shared.b16 {%0,%1}, [%2];"
                 : "=r"(r0), "=r"(r1) : "r"(a));
}
__device__ __forceinline__ void ldsm_x2t(uint32_t& r0, uint32_t& r1, uint32_t a) {
    asm volatile("ldmatrix.sync.aligned.m8n8.x2.trans.shared.b16 {%0,%1}, [%2];"
                 : "=r"(r0), "=r"(r1) : "r"(a));
}
__device__ __forceinline__ void mma_bf16(float* c, uint32_t a0, uint32_t a1, uint32_t a2, uint32_t a3,
                                         uint32_t b0, uint32_t b1) {
    asm volatile(
        "mma.sync.aligned.m16n8k16.row.col.f32.bf16.bf16.f32 "
        "{%0,%1,%2,%3}, {%4,%5,%6,%7}, {%8,%9}, {%0,%1,%2,%3};"
        : "+f"(c[0]), "+f"(c[1]), "+f"(c[2]), "+f"(c[3])
        : "r"(a0), "r"(a1), "r"(a2), "r"(a3), "r"(b0), "r"(b1));
}

// ---------------------------------------------------------------------------
// prep: ONE kernel — flag reset + ALL fp32->bf16 hi/lo splits
// ---------------------------------------------------------------------------
#define N_X4   (MROWS * DD / 4)
#define N_WX4  (DD * NG / 4)
#define N_AWX4 (DD * NAG / 4)
#define N_TOT4 (N_X4 + 2 * N_WX4 + 2 * N_AWX4)

__device__ __forceinline__ void split4(const float4* s4, bf16* hi, bf16* lo, int i) {
    float4 v = s4[i];
    bf16 hx = __float2bfloat16_rn(v.x);
    bf16 hy = __float2bfloat16_rn(v.y);
    bf16 hz = __float2bfloat16_rn(v.z);
    bf16 hw = __float2bfloat16_rn(v.w);
    __nv_bfloat162 hp0, hp1, lp0, lp1;
    hp0.x = hx; hp0.y = hy; hp1.x = hz; hp1.y = hw;
    lp0.x = __float2bfloat16_rn(v.x - __bfloat162float(hx));
    lp0.y = __float2bfloat16_rn(v.y - __bfloat162float(hy));
    lp1.x = __float2bfloat16_rn(v.z - __bfloat162float(hz));
    lp1.y = __float2bfloat16_rn(v.w - __bfloat162float(hw));
    ((uint2*)hi)[i] = make_uint2(*(uint32_t*)&hp0, *(uint32_t*)&hp1);
    ((uint2*)lo)[i] = make_uint2(*(uint32_t*)&lp0, *(uint32_t*)&lp1);
}

__global__ void prep(const float* __restrict__ x,
                     const float* __restrict__ Wx_f, const float* __restrict__ Wx_b,
                     const float* __restrict__ aWx_f, const float* __restrict__ aWx_b)
{
    int gid = blockIdx.x * blockDim.x + threadIdx.x;
    if (gid < 2 * 64 * 32) ((unsigned*)g_mflag)[gid] = 0u;
    if (gid < 2 * 32 * 32) ((unsigned*)g_aflag)[gid] = 0u;

    for (int i = gid; i < N_TOT4; i += gridDim.x * blockDim.x) {
        int r = i;
        if (r < N_X4) { split4((const float4*)x, g_Xhi, g_Xlo, r); continue; }
        r -= N_X4;
        if (r < N_WX4) { split4((const float4*)Wx_f, g_Wxhi[0], g_Wxlo[0], r); continue; }
        r -= N_WX4;
        if (r < N_WX4) { split4((const float4*)Wx_b, g_Wxhi[1], g_Wxlo[1], r); continue; }
        r -= N_WX4;
        if (r < N_AWX4) { split4((const float4*)aWx_f, g_aWxhi[0], g_aWxlo[0], r); continue; }
        r -= N_AWX4;
        split4((const float4*)aWx_b, g_aWxhi[1], g_aWxlo[1], r);
    }
}

// ---------------------------------------------------------------------------
// bf16-split GEMM, 2 CTAs/SM, 2-stage cp.async pipeline (loads for slab k+1
// overlap MMAs of slab k).
// ---------------------------------------------------------------------------
#define ASTRIDE 24
#define BSTRIDE 136
#define A_ELEMS (128 * ASTRIDE)
#define B_ELEMS (16 * BSTRIDE)

__global__ void __launch_bounds__(256, 2) gemm_mma(
    int bsel, const float* __restrict__ bias, int csel, int N, int K)
{
    const bf16 *Ahi = g_Xhi, *Alo = g_Xlo;
    const bf16 *Bhi, *Blo;
    float* C;
    switch (bsel) {
        case 0:  Bhi = g_Wxhi[0];  Blo = g_Wxlo[0];  break;
        case 1:  Bhi = g_Wxhi[1];  Blo = g_Wxlo[1];  break;
        case 2:  Bhi = g_aWxhi[0]; Blo = g_aWxlo[0]; break;
        default: Bhi = g_aWxhi[1]; Blo = g_aWxlo[1]; break;
    }
    switch (csel) {
        case 0:  C = g_xg[0];  break;
        case 1:  C = g_xg[1];  break;
        case 2:  C = g_axg[0]; break;
        default: C = g_axg[1]; break;
    }

    __shared__ __align__(16) bf16 sAh[2][A_ELEMS], sAl[2][A_ELEMS];
    __shared__ __align__(16) bf16 sBh[2][B_ELEMS], sBl[2][B_ELEMS];

    const int tid  = threadIdx.x;
    const int w    = tid >> 5, lane = tid & 31;
    const int wm   = w & 1,    wn   = w >> 1;
    const int bm   = blockIdx.y * 128;
    const int bn   = blockIdx.x * 128;

    const int arow = tid >> 1, ahalf = tid & 1;
    const int brow = tid >> 4, bseg  = tid & 15;

    // Per-thread staging addresses (stage 0; stage 1 = +byte size of one stage set)
    const uint32_t aDstH0 = cvta_s(&sAh[0][arow * ASTRIDE + ahalf * 8]);
    const uint32_t aDstL0 = cvta_s(&sAl[0][arow * ASTRIDE + ahalf * 8]);
    const uint32_t bDstH0 = cvta_s(&sBh[0][brow * BSTRIDE + bseg * 8]);
    const uint32_t bDstL0 = cvta_s(&sBl[0][brow * BSTRIDE + bseg * 8]);
    const uint32_t aStageBytes = (uint32_t)(A_ELEMS * 2);
    const uint32_t bStageBytes = (uint32_t)(B_ELEMS * 2);

    const bf16* aSrcH = Ahi + (size_t)(bm + arow) * K + ahalf * 8;
    const bf16* aSrcL = Alo + (size_t)(bm + arow) * K + ahalf * 8;
    const bf16* bSrcH = Bhi + (size_t)brow * N + bn + bseg * 8;
    const bf16* bSrcL = Blo + (size_t)brow * N + bn + bseg * 8;

    float acc[4][4][4];
#pragma unroll
    for (int i = 0; i < 4; i++)
#pragma unroll
        for (int j = 0; j < 4; j++) {
            acc[i][j][0] = 0.f; acc[i][j][1] = 0.f; acc[i][j][2] = 0.f; acc[i][j][3] = 0.f;
        }

    const uint32_t aBaseH = cvta_s(sAh[0]) + (uint32_t)(((wm * 64 + (lane & 15)) * ASTRIDE + ((lane >> 4) << 3)) * 2);
    const uint32_t aBaseL = cvta_s(sAl[0]) + (uint32_t)(((wm * 64 + (lane & 15)) * ASTRIDE + ((lane >> 4) << 3)) * 2);
    const uint32_t bBaseH = cvta_s(sBh[0]) + (uint32_t)((((lane & 15)) * BSTRIDE + wn * 32) * 2);
    const uint32_t bBaseL = cvta_s(sBl[0]) + (uint32_t)((((lane & 15)) * BSTRIDE + wn * 32) * 2);

    const int nIter = K >> 4;

    // prologue: stage 0 loads for slab 0
    cp16(aDstH0, aSrcH);
    cp16(aDstL0, aSrcL);
    cp16(bDstH0, bSrcH);
    cp16(bDstL0, bSrcL);
    cp_commit();

#pragma unroll 1
    for (int it = 0; it < nIter; it++) {
        const int cur = it & 1;
        if (it + 1 < nIter) {
            const int nxt = (it + 1) & 1;
            const int k0 = (it + 1) << 4;
            cp16(aDstH0 + nxt * aStageBytes, aSrcH + k0);
            cp16(aDstL0 + nxt * aStageBytes, aSrcL + k0);
            cp16(bDstH0 + nxt * bStageBytes, bSrcH + (size_t)k0 * N);
            cp16(bDstL0 + nxt * bStageBytes, bSrcL + (size_t)k0 * N);
            cp_commit();
            cp_wait1();
        } else {
            cp_wait0();
        }
        __syncthreads();

        const uint32_t aOff = (uint32_t)cur * aStageBytes;
        const uint32_t bOff = (uint32_t)cur * bStageBytes;
        uint32_t bh[4][2], bl[4][2];
#pragma unroll
        for (int nt = 0; nt < 4; nt++) {
            ldsm_x2t(bh[nt][0], bh[nt][1], bBaseH + bOff + nt * 16);
            ldsm_x2t(bl[nt][0], bl[nt][1], bBaseL + bOff + nt * 16);
        }
#pragma unroll
        for (int mt = 0; mt < 4; mt++) {
            uint32_t a0, a1, a2, a3, l0, l1, l2, l3;
            ldsm_x4(a0, a1, a2, a3, aBaseH + aOff + mt * (16 * ASTRIDE * 2));
            ldsm_x4(l0, l1, l2, l3, aBaseL + aOff + mt * (16 * ASTRIDE * 2));
#pragma unroll
            for (int nt = 0; nt < 4; nt++) {
                mma_bf16(acc[mt][nt], a0, a1, a2, a3, bh[nt][0], bh[nt][1]);
                mma_bf16(acc[mt][nt], a0, a1, a2, a3, bl[nt][0], bl[nt][1]);
                mma_bf16(acc[mt][nt], l0, l1, l2, l3, bh[nt][0], bh[nt][1]);
            }
        }
        __syncthreads();   // stage cur free for iteration it+2's loads
    }

#pragma unroll
    for (int mt = 0; mt < 4; mt++)
#pragma unroll
        for (int nt = 0; nt < 4; nt++) {
            int m = bm + wm * 64 + mt * 16 + (lane >> 2);
            int n = bn + wn * 32 + nt * 8 + ((lane & 3) << 1);
            float b0 = bias ? bias[n] : 0.f;
            float b1 = bias ? bias[n + 1] : 0.f;
            *(float2*)&C[(size_t)m * N + n] = make_float2(acc[mt][nt][0] + b0, acc[mt][nt][1] + b1);
            *(float2*)&C[(size_t)(m + 8) * N + n] = make_float2(acc[mt][nt][2] + b0, acc[mt][nt][3] + b1);
        }
}

// ---------------------------------------------------------------------------
// Adaptive scan. 64 CTAs (32/dir) x 128 threads, flag-array barrier.
// ---------------------------------------------------------------------------
__global__ void __launch_bounds__(128, 1) ascan(
    const float* __restrict__ aWh_f, const float* __restrict__ aWh_b)
{
    const int bid = blockIdx.x;
    const int dir = bid >> 5;
    const int j   = bid & 31;
    const int c0  = j * 4;
    const float* aWh = dir ? aWh_b : aWh_f;
    const float* axg = g_axg[dir];

    __shared__ float aW2[16 * 132];
    __shared__ float ah_sh[32 * 132];

    const int tid = threadIdx.x;
    for (int i = tid; i < 16 * 128; i += 128) {
        int k = i >> 4, c = i & 15;
        int g = c >> 2, hc = c & 3;
        aW2[c * 132 + k] = aWh[k * NAG + (g << 7) + c0 + hc];
    }

    const int b  = tid >> 2;
    const int hc = tid & 3;
    float acst = 0.f;

    for (int t = 0; t < TT; t++) {
        const int p = t & 1;
        if (t > 0 && tid < 32) poll_flag(&g_aflag[dir][tid][0], (unsigned)t);
        __syncthreads();

        if (t == 0) {
            for (int i = tid; i < 32 * 132; i += 128) ah_sh[i] = 0.f;
        } else {
            const float* src = g_ahst[dir][p];
            uint32_t dbase = cvta_s(ah_sh);
            for (int i = tid; i < (BB * AA) / 4; i += 128) {
                int el = i * 4;
                int bb = el >> 7, k = el & 127;
                cp16(dbase + (uint32_t)((bb * 132 + k) * 4), src + el);
            }
            cp_commit();
            cp_wait0();
        }
        __syncthreads();

        const int rowoff = ((b << 8) + t) * NAG + c0 + hc;
        float acc0 = axg[rowoff];
        float acc1 = axg[rowoff + 128];
        float acc2 = axg[rowoff + 256];
        float acc3 = axg[rowoff + 384];

        const float* hp = &ah_sh[b * 132];
        const float* w0 = &aW2[(0 + hc) * 132];
        const float* w1 = &aW2[(4 + hc) * 132];
        const float* w2 = &aW2[(8 + hc) * 132];
        const float* w3 = &aW2[(12 + hc) * 132];
#pragma unroll 8
        for (int k = 0; k < 128; k += 4) {
            float4 h4 = *(const float4*)(hp + k);
            float4 a4 = *(const float4*)(w0 + k);
            float4 b4 = *(const float4*)(w1 + k);
            float4 c4 = *(const float4*)(w2 + k);
            float4 d4 = *(const float4*)(w3 + k);
            acc0 += h4.x * a4.x + h4.y * a4.y + h4.z * a4.z + h4.w * a4.w;
            acc1 += h4.x * b4.x + h4.y * b4.y + h4.z * b4.z + h4.w * b4.w;
            acc2 += h4.x * c4.x + h4.y * c4.y + h4.z * c4.z + h4.w * c4.w;
            acc3 += h4.x * d4.x + h4.y * d4.y + h4.z * d4.z + h4.w * d4.w;
        }

        float ig = sigm(acc0), fg = sigm(acc1), og = sigm(acc3);
        acst = fg * acst + ig * tanhf(acc2);
        float ahv = og * tanhf(acst);

        const int ci = c0 + hc;
        __stcg(&g_ahst[dir][1 - p][(b << 7) + ci], ahv);
        bf16 hh = __float2bfloat16_rn(ahv);
        g_ahT_hi[dir][t][(b << 7) + ci] = hh;
        g_ahT_lo[dir][t][(b << 7) + ci] = __float2bfloat16_rn(ahv - __bfloat162float(hh));

        __syncthreads();
        if (tid == 0) st_release_gpu(&g_aflag[dir][j][0], (unsigned)(t + 1));
    }
}

// ---------------------------------------------------------------------------
// Main scan. Merged polls (disjoint thread ranges) + single staging group
// per step: 4 __syncthreads + 1 cp-wait per step.
// ---------------------------------------------------------------------------
#define WSTRIDE 520
#define ZSTRIDE 136
#define MS_SMEM ((4 * 32 * WSTRIDE) * 2 + (4 * 32 * ZSTRIDE) * 2 + 32 * 36 * 4)

__global__ void __launch_bounds__(256, 1) mscan_mma(
    const float* __restrict__ Wh_f, const float* __restrict__ Wh_b,
    const float* __restrict__ Wz_f, const float* __restrict__ Wz_b,
    float* __restrict__ out)
{
    extern __shared__ __align__(16) char smraw[];
    bf16* Whi_s = (bf16*)smraw;                   // [32][520]
    bf16* Wlo_s = Whi_s + 32 * WSTRIDE;
    bf16* Hhi_s = Wlo_s + 32 * WSTRIDE;           // [32][520]
    bf16* Hlo_s = Hhi_s + 32 * WSTRIDE;
    bf16* Zhi_s = Hlo_s + 32 * WSTRIDE;           // [32][136] Wz slice, [c][k]
    bf16* Zlo_s = Zhi_s + 32 * ZSTRIDE;
    bf16* Ehi_s = Zlo_s + 32 * ZSTRIDE;           // [32][136] ah_t, [b][k]
    bf16* Elo_s = Ehi_s + 32 * ZSTRIDE;
    float* gbuf = (float*)(Elo_s + 32 * ZSTRIDE); // [32][36]

    const int bid = blockIdx.x;
    const int dir = bid >> 6;
    const int j   = bid & 63;
    const int hc0 = j * 8;
    const float* Wh = dir ? Wh_b : Wh_f;
    const float* Wz = dir ? Wz_b : Wz_f;
    const float* xg = g_xg[dir];

    const int tid  = threadIdx.x;
    const int w    = tid >> 5, lane = tid & 31;
    const int mh   = w & 1, g = w >> 1;

    // Prologue: split Wh slice (K=512) and Wz slice (K=128) into smem
    for (int i = tid; i < 32 * 512; i += 256) {
        int c = i & 31, k = i >> 5;
        float wv = Wh[(size_t)k * NG + ((c >> 3) << 9) + hc0 + (c & 7)];
        bf16 h = __float2bfloat16_rn(wv);
        Whi_s[c * WSTRIDE + k] = h;
        Wlo_s[c * WSTRIDE + k] = __float2bfloat16_rn(wv - __bfloat162float(h));
    }
    for (int i = tid; i < 32 * 128; i += 256) {
        int c = i & 31, k = i >> 5;
        float wv = Wz[(size_t)k * NG + ((c >> 3) << 9) + hc0 + (c & 7)];
        bf16 h = __float2bfloat16_rn(wv);
        Zhi_s[c * ZSTRIDE + k] = h;
        Zlo_s[c * ZSTRIDE + k] = __float2bfloat16_rn(wv - __bfloat162float(h));
    }
    __syncthreads();

    const uint32_t aH = cvta_s(Hhi_s) + (uint32_t)(((mh * 16 + (lane & 15)) * WSTRIDE + ((lane >> 4) << 3)) * 2);
    const uint32_t aL = cvta_s(Hlo_s) + (uint32_t)(((mh * 16 + (lane & 15)) * WSTRIDE + ((lane >> 4) << 3)) * 2);
    const uint32_t bH = cvta_s(Whi_s) + (uint32_t)(((g * 8 + (lane & 7)) * WSTRIDE + (lane & 8)) * 2);
    const uint32_t bL = cvta_s(Wlo_s) + (uint32_t)(((g * 8 + (lane & 7)) * WSTRIDE + (lane & 8)) * 2);
    const uint32_t aEH = cvta_s(Ehi_s) + (uint32_t)(((mh * 16 + (lane & 15)) * ZSTRIDE + ((lane >> 4) << 3)) * 2);
    const uint32_t aEL = cvta_s(Elo_s) + (uint32_t)(((mh * 16 + (lane & 15)) * ZSTRIDE + ((lane >> 4) << 3)) * 2);
    const uint32_t bZH = cvta_s(Zhi_s) + (uint32_t)(((g * 8 + (lane & 7)) * ZSTRIDE + (lane & 8)) * 2);
    const uint32_t bZL = cvta_s(Zlo_s) + (uint32_t)(((g * 8 + (lane & 7)) * ZSTRIDE + (lane & 8)) * 2);

    const uint32_t eHiBase = cvta_s(Ehi_s);
    const uint32_t eLoBase = cvta_s(Elo_s);
    const uint32_t hHiBase = cvta_s(Hhi_s);
    const uint32_t hLoBase = cvta_s(Hlo_s);

    // Hoist loop-invariant Wz B fragments into registers (8 k-chunks)
    uint32_t zbh[8][2], zbl[8][2];
#pragma unroll
    for (int c = 0; c < 8; c++) {
        ldsm_x2(zbh[c][0], zbh[c][1], bZH + c * 32);
        ldsm_x2(zbl[c][0], zbl[c][1], bZL + c * 32);
    }

    const int b  = tid >> 3;
    const int hc = tid & 7;
    float cst = 0.f;

    for (int t = 0; t < TT; t++) {
        const int p = t & 1;

        // prefetch xg gate rows (independent of everything)
        const float* xr = xg + (size_t)((b << 8) + t) * NG + hc0 + hc;
        float x0 = xr[0], x1 = xr[512], x2 = xr[1024], x3 = xr[1536];

        // 1. merged polls on disjoint thread ranges
        if (tid < 32) {
            poll_flag(&g_aflag[dir][tid][0], (unsigned)(t + 1));
        } else if (t > 0 && tid >= 64 && tid < 128) {
            poll_flag(&g_mflag[dir][tid - 64][0], (unsigned)t);
        }
        __syncthreads();

        // 2. stage E + h in one cp.async group
        {
            const bf16* eh = g_ahT_hi[dir][t];
            const bf16* el = g_ahT_lo[dir][t];
            for (int i = tid; i < 512; i += 256) {
                int e = i << 3;
                int bb = e >> 7, k = e & 127;
                uint32_t off = (uint32_t)((bb * ZSTRIDE + k) * 2);
                cp16(eHiBase + off, eh + e);
                cp16(eLoBase + off, el + e);
            }
        }
        if (t == 0) {
            uint4 z = make_uint4(0, 0, 0, 0);
            for (int i = tid; i < (32 * WSTRIDE) / 8; i += 256) {
                ((uint4*)Hhi_s)[i] = z;
                ((uint4*)Hlo_s)[i] = z;
            }
        } else {
            const bf16* sh = g_hsth[dir][p];
            const bf16* sl = g_hstl[dir][p];
            for (int i = tid; i < 2048; i += 256) {
                int e = i << 3;
                int bb = e >> 9, k = e & 511;
                uint32_t off = (uint32_t)((bb * WSTRIDE + k) * 2);
                cp16(hHiBase + off, sh + e);
                cp16(hLoBase + off, sl + e);
            }
        }
        cp_commit();
        cp_wait0();
        __syncthreads();

        // 3. Wz MMAs (E) + Wh MMAs (h)
        float c4[4] = {0.f, 0.f, 0.f, 0.f};
#pragma unroll
        for (int c = 0; c < 8; c++) {
            uint32_t a0, a1, a2, a3, l0, l1, l2, l3;
            ldsm_x4(a0, a1, a2, a3, aEH + c * 32);
            ldsm_x4(l0, l1, l2, l3, aEL + c * 32);
            mma_bf16(c4, a0, a1, a2, a3, zbh[c][0], zbh[c][1]);
            mma_bf16(c4, a0, a1, a2, a3, zbl[c][0], zbl[c][1]);
            mma_bf16(c4, l0, l1, l2, l3, zbh[c][0], zbh[c][1]);
        }
#pragma unroll 4
        for (int k0 = 0; k0 < 512; k0 += 16) {
            uint32_t ah0, ah1, ah2, ah3, al0, al1, al2, al3, bh0, bh1, bl0, bl1;
            ldsm_x4(ah0, ah1, ah2, ah3, aH + k0 * 2);
            ldsm_x4(al0, al1, al2, al3, aL + k0 * 2);
            ldsm_x2(bh0, bh1, bH + k0 * 2);
            ldsm_x2(bl0, bl1, bL + k0 * 2);
            mma_bf16(c4, ah0, ah1, ah2, ah3, bh0, bh1);
            mma_bf16(c4, ah0, ah1, ah2, ah3, bl0, bl1);
            mma_bf16(c4, al0, al1, al2, al3, bh0, bh1);
        }

        // 4. scatter fragments to gate buffer
        {
            int m = mh * 16 + (lane >> 2);
            int nc = g * 8 + ((lane & 3) << 1);
            gbuf[m * 36 + nc]     = c4[0];
            gbuf[m * 36 + nc + 1] = c4[1];
            gbuf[(m + 8) * 36 + nc]     = c4[2];
            gbuf[(m + 8) * 36 + nc + 1] = c4[3];
        }
        __syncthreads();

        // 5. LSTM cell; publish h + flag first, out store after
        float hv;
        {
            float gi = gbuf[b * 36 + hc]      + x0;
            float gf = gbuf[b * 36 + 8 + hc]  + x1;
            float gu = gbuf[b * 36 + 16 + hc] + x2;
            float go = gbuf[b * 36 + 24 + hc] + x3;
            cst = sigm(gf) * cst + sigm(gi) * tanhf(gu);
            hv = sigm(go) * tanhf(cst);

            bf16 hh = __float2bfloat16_rn(hv);
            bf16 hl = __float2bfloat16_rn(hv - __bfloat162float(hh));
            int hidx = (b << 9) + hc0 + hc;
            __stcg(&g_hsth[dir][1 - p][hidx], hh);
            __stcg(&g_hstl[dir][1 - p][hidx], hl);
        }
        __syncthreads();
        if (tid == 0) st_release_gpu(&g_mflag[dir][j][0], (unsigned)(t + 1));

        out[(size_t)((b << 8) + t) * 1024 + (dir << 9) + hc0 + hc] = hv;
    }
}

// ---------------------------------------------------------------------------
static cudaStream_t s_side = nullptr;
static cudaEvent_t  s_evA  = nullptr;
static cudaEvent_t  s_evB  = nullptr;

extern "C" void kernel_launch(void* const* d_in, const int* in_sizes, int n_in,
                              void* d_out, int out_size)
{
    const float* x     = (const float*)d_in[0];
    const float* Wx_f  = (const float*)d_in[1];
    const float* Wh_f  = (const float*)d_in[2];
    const float* b_f   = (const float*)d_in[3];
    const float* aWx_f = (const float*)d_in[4];
    const float* aWh_f = (const float*)d_in[5];
    const float* ab_f  = (const float*)d_in[6];
    const float* Wz_f  = (const float*)d_in[7];
    const float* Wx_b  = (const float*)d_in[8];
    const float* Wh_b  = (const float*)d_in[9];
    const float* b_b   = (const float*)d_in[10];
    const float* aWx_b = (const float*)d_in[11];
    const float* aWh_b = (const float*)d_in[12];
    const float* ab_b  = (const float*)d_in[13];
    const float* Wz_b  = (const float*)d_in[14];
    float* out = (float*)d_out;

    if (!s_side) {
        cudaStreamCreateWithFlags(&s_side, cudaStreamNonBlocking);
        cudaEventCreateWithFlags(&s_evA, cudaEventDisableTiming);
        cudaEventCreateWithFlags(&s_evB, cudaEventDisableTiming);
        cudaFuncSetAttribute(mscan_mma, cudaFuncAttributeMaxDynamicSharedMemorySize, MS_SMEM);
    }

    // [1] prep: flag reset + all bf16 splits
    prep<<<1664, 1024>>>(x, Wx_f, Wx_b, aWx_f, aWx_b);

    // [2-3] adaptive x-projections
    gemm_mma<<<dim3(NAG / 128, MROWS / 128), 256>>>(2, ab_f, 2, NAG, DD);
    gemm_mma<<<dim3(NAG / 128, MROWS / 128), 256>>>(3, ab_b, 3, NAG, DD);
    cudaEventRecord(s_evA, 0);

    // [4-5] main x-projections
    gemm_mma<<<dim3(NG / 128, MROWS / 128), 256>>>(0, b_f, 0, NG, DD);
    gemm_mma<<<dim3(NG / 128, MROWS / 128), 256>>>(1, b_b, 1, NG, DD);

    // [6] main scan
    mscan_mma<<<128, 256, MS_SMEM>>>(Wh_f, Wh_b, Wz_f, Wz_b, out);

    // [7] adaptive scan on the side stream (overlaps xg GEMMs + mscan)
    cudaStreamWaitEvent(s_side, s_evA, 0);
    ascan<<<64, 128, 0, s_side>>>(aWh_f, aWh_b);
    cudaEventRecord(s_evB, s_side);

    // join the side branch
    cudaStreamWaitEvent(0, s_evB, 0);
}

// round 12
// speedup vs baseline: 1.0050x; 1.0050x over previous
#include <cuda_runtime.h>
#include <cuda_bf16.h>
#include <cstdint>
#include <math.h>

// ---------------------------------------------------------------------------
// Problem constants
// ---------------------------------------------------------------------------
#define BB   32
#define TT   256
#define DD   512
#define HH   512
#define AA   128
#define MROWS 8192      // B*T
#define NG    2048      // 4H
#define NAG   512       // 4A

typedef __nv_bfloat16 bf16;

// ---------------------------------------------------------------------------
// Static device workspace
// ---------------------------------------------------------------------------
__device__ float g_xg [2][MROWS * NG];    // per dir: x@Wx + b. row = b*T+t
__device__ float g_axg[2][MROWS * NAG];   // per dir: x@aWx + ab. row = b*T+t
__device__ float g_ahst[2][2][BB * AA];   // double-buffered adaptive hidden state
__device__ bf16  g_hsth[2][2][BB * HH];   // double-buffered main hidden (hi)
__device__ bf16  g_hstl[2][2][BB * HH];   // double-buffered main hidden (lo)

// Epoch flags: one 128B-padded slot per CTA
__device__ unsigned g_mflag[2][64][32];   // mscan CTAs
__device__ unsigned g_aflag[2][32][32];   // ascan CTAs

// bf16 hi/lo splits
__device__ bf16 g_Xhi [MROWS * DD],  g_Xlo [MROWS * DD];
__device__ bf16 g_Wxhi[2][DD * NG],  g_Wxlo[2][DD * NG];
__device__ bf16 g_aWxhi[2][DD * NAG], g_aWxlo[2][DD * NAG];

// t-major adaptive hidden stream for mscan consumption: [dir][t][b*128+c]
__device__ bf16 g_ahT_hi[2][TT][BB * AA];
__device__ bf16 g_ahT_lo[2][TT][BB * AA];

__device__ __forceinline__ float sigm(float x) { return 1.f / (1.f + expf(-x)); }

// --- release/acquire primitives -------------------------------------------
__device__ __forceinline__ void st_release_gpu(unsigned* p, unsigned v) {
    asm volatile("st.release.gpu.global.u32 [%0], %1;" :: "l"(p), "r"(v));
}
__device__ __forceinline__ unsigned ld_acquire_gpu(const unsigned* p) {
    unsigned v;
    asm volatile("ld.acquire.gpu.global.u32 %0, [%1];" : "=r"(v) : "l"(p));
    return v;
}
__device__ __forceinline__ void poll_flag(const unsigned* p, unsigned tgt) {
    int s = 0;
    while (ld_acquire_gpu(p) < tgt) {
        if (++s > 16) __nanosleep(40);
    }
}

// --- cp.async (16B, L2-direct) --------------------------------------------
__device__ __forceinline__ void cp16(uint32_t dst, const void* src) {
    asm volatile("cp.async.cg.shared.global [%0], [%1], 16;" :: "r"(dst), "l"(src));
}
__device__ __forceinline__ void cp_commit() {
    asm volatile("cp.async.commit_group;");
}
__device__ __forceinline__ void cp_wait0() {
    asm volatile("cp.async.wait_group 0;" ::: "memory");
}
__device__ __forceinline__ void cp_wait1() {
    asm volatile("cp.async.wait_group 1;" ::: "memory");
}

// ---------------------------------------------------------------------------
// mma.sync helpers (bf16, m16n8k16, fp32 accumulate)
// ---------------------------------------------------------------------------
__device__ __forceinline__ uint32_t cvta_s(const void* p) {
    return (uint32_t)__cvta_generic_to_shared(p);
}
__device__ __forceinline__ void ldsm_x4(uint32_t& r0, uint32_t& r1, uint32_t& r2, uint32_t& r3, uint32_t a) {
    asm volatile("ldmatrix.sync.aligned.m8n8.x4.shared.b16 {%0,%1,%2,%3}, [%4];"
                 : "=r"(r0), "=r"(r1), "=r"(r2), "=r"(r3) : "r"(a));
}
__device__ __forceinline__ void ldsm_x2(uint32_t& r0, uint32_t& r1, uint32_t a) {
    asm volatile("ldmatrix.sync.aligned.m8n8.x2.shared.b16 {%0,%1}, [%2];"
                 : "=r"(r0), "=r"(r1) : "r"(a));
}
__device__ __forceinline__ void ldsm_x2t(uint32_t& r0, uint32_t& r1, uint32_t a) {
    asm volatile("ldmatrix.sync.aligned.m8n8.x2.trans.shared.b16 {%0,%1}, [%2];"
                 : "=r"(r0), "=r"(r1) : "r"(a));
}
__device__ __forceinline__ void mma_bf16(float* c, uint32_t a0, uint32_t a1, uint32_t a2, uint32_t a3,
                                         uint32_t b0, uint32_t b1) {
    asm volatile(
        "mma.sync.aligned.m16n8k16.row.col.f32.bf16.bf16.f32 "
        "{%0,%1,%2,%3}, {%4,%5,%6,%7}, {%8,%9}, {%0,%1,%2,%3};"
        : "+f"(c[0]), "+f"(c[1]), "+f"(c[2]), "+f"(c[3])
        : "r"(a0), "r"(a1), "r"(a2), "r"(a3), "r"(b0), "r"(b1));
}

// ---------------------------------------------------------------------------
// prep: ONE kernel — flag reset + ALL fp32->bf16 hi/lo splits
// ---------------------------------------------------------------------------
#define N_X4   (MROWS * DD / 4)
#define N_WX4  (DD * NG / 4)
#define N_AWX4 (DD * NAG / 4)
#define N_TOT4 (N_X4 + 2 * N_WX4 + 2 * N_AWX4)

__device__ __forceinline__ void split4(const float4* s4, bf16* hi, bf16* lo, int i) {
    float4 v = s4[i];
    bf16 hx = __float2bfloat16_rn(v.x);
    bf16 hy = __float2bfloat16_rn(v.y);
    bf16 hz = __float2bfloat16_rn(v.z);
    bf16 hw = __float2bfloat16_rn(v.w);
    __nv_bfloat162 hp0, hp1, lp0, lp1;
    hp0.x = hx; hp0.y = hy; hp1.x = hz; hp1.y = hw;
    lp0.x = __float2bfloat16_rn(v.x - __bfloat162float(hx));
    lp0.y = __float2bfloat16_rn(v.y - __bfloat162float(hy));
    lp1.x = __float2bfloat16_rn(v.z - __bfloat162float(hz));
    lp1.y = __float2bfloat16_rn(v.w - __bfloat162float(hw));
    ((uint2*)hi)[i] = make_uint2(*(uint32_t*)&hp0, *(uint32_t*)&hp1);
    ((uint2*)lo)[i] = make_uint2(*(uint32_t*)&lp0, *(uint32_t*)&lp1);
}

__global__ void prep(const float* __restrict__ x,
                     const float* __restrict__ Wx_f, const float* __restrict__ Wx_b,
                     const float* __restrict__ aWx_f, const float* __restrict__ aWx_b)
{
    int gid = blockIdx.x * blockDim.x + threadIdx.x;
    if (gid < 2 * 64 * 32) ((unsigned*)g_mflag)[gid] = 0u;
    if (gid < 2 * 32 * 32) ((unsigned*)g_aflag)[gid] = 0u;

    for (int i = gid; i < N_TOT4; i += gridDim.x * blockDim.x) {
        int r = i;
        if (r < N_X4) { split4((const float4*)x, g_Xhi, g_Xlo, r); continue; }
        r -= N_X4;
        if (r < N_WX4) { split4((const float4*)Wx_f, g_Wxhi[0], g_Wxlo[0], r); continue; }
        r -= N_WX4;
        if (r < N_WX4) { split4((const float4*)Wx_b, g_Wxhi[1], g_Wxlo[1], r); continue; }
        r -= N_WX4;
        if (r < N_AWX4) { split4((const float4*)aWx_f, g_aWxhi[0], g_aWxlo[0], r); continue; }
        r -= N_AWX4;
        split4((const float4*)aWx_b, g_aWxhi[1], g_aWxlo[1], r);
    }
}

// ---------------------------------------------------------------------------
// bf16-split GEMM, 2 CTAs/SM, 2-stage cp.async pipeline (R11 version — measured
// 171us on the NG GEMM, tensor 56.8%).
// ---------------------------------------------------------------------------
#define ASTRIDE 24
#define BSTRIDE 136
#define A_ELEMS (128 * ASTRIDE)
#define B_ELEMS (16 * BSTRIDE)

__global__ void __launch_bounds__(256, 2) gemm_mma(
    int bsel, const float* __restrict__ bias, int csel, int N, int K)
{
    const bf16 *Ahi = g_Xhi, *Alo = g_Xlo;
    const bf16 *Bhi, *Blo;
    float* C;
    switch (bsel) {
        case 0:  Bhi = g_Wxhi[0];  Blo = g_Wxlo[0];  break;
        case 1:  Bhi = g_Wxhi[1];  Blo = g_Wxlo[1];  break;
        case 2:  Bhi = g_aWxhi[0]; Blo = g_aWxlo[0]; break;
        default: Bhi = g_aWxhi[1]; Blo = g_aWxlo[1]; break;
    }
    switch (csel) {
        case 0:  C = g_xg[0];  break;
        case 1:  C = g_xg[1];  break;
        case 2:  C = g_axg[0]; break;
        default: C = g_axg[1]; break;
    }

    __shared__ __align__(16) bf16 sAh[2][A_ELEMS], sAl[2][A_ELEMS];
    __shared__ __align__(16) bf16 sBh[2][B_ELEMS], sBl[2][B_ELEMS];

    const int tid  = threadIdx.x;
    const int w    = tid >> 5, lane = tid & 31;
    const int wm   = w & 1,    wn   = w >> 1;
    const int bm   = blockIdx.y * 128;
    const int bn   = blockIdx.x * 128;

    const int arow = tid >> 1, ahalf = tid & 1;
    const int brow = tid >> 4, bseg  = tid & 15;

    const uint32_t aDstH0 = cvta_s(&sAh[0][arow * ASTRIDE + ahalf * 8]);
    const uint32_t aDstL0 = cvta_s(&sAl[0][arow * ASTRIDE + ahalf * 8]);
    const uint32_t bDstH0 = cvta_s(&sBh[0][brow * BSTRIDE + bseg * 8]);
    const uint32_t bDstL0 = cvta_s(&sBl[0][brow * BSTRIDE + bseg * 8]);
    const uint32_t aStageBytes = (uint32_t)(A_ELEMS * 2);
    const uint32_t bStageBytes = (uint32_t)(B_ELEMS * 2);

    const bf16* aSrcH = Ahi + (size_t)(bm + arow) * K + ahalf * 8;
    const bf16* aSrcL = Alo + (size_t)(bm + arow) * K + ahalf * 8;
    const bf16* bSrcH = Bhi + (size_t)brow * N + bn + bseg * 8;
    const bf16* bSrcL = Blo + (size_t)brow * N + bn + bseg * 8;

    float acc[4][4][4];
#pragma unroll
    for (int i = 0; i < 4; i++)
#pragma unroll
        for (int j = 0; j < 4; j++) {
            acc[i][j][0] = 0.f; acc[i][j][1] = 0.f; acc[i][j][2] = 0.f; acc[i][j][3] = 0.f;
        }

    const uint32_t aBaseH = cvta_s(sAh[0]) + (uint32_t)(((wm * 64 + (lane & 15)) * ASTRIDE + ((lane >> 4) << 3)) * 2);
    const uint32_t aBaseL = cvta_s(sAl[0]) + (uint32_t)(((wm * 64 + (lane & 15)) * ASTRIDE + ((lane >> 4) << 3)) * 2);
    const uint32_t bBaseH = cvta_s(sBh[0]) + (uint32_t)((((lane & 15)) * BSTRIDE + wn * 32) * 2);
    const uint32_t bBaseL = cvta_s(sBl[0]) + (uint32_t)((((lane & 15)) * BSTRIDE + wn * 32) * 2);

    const int nIter = K >> 4;

    cp16(aDstH0, aSrcH);
    cp16(aDstL0, aSrcL);
    cp16(bDstH0, bSrcH);
    cp16(bDstL0, bSrcL);
    cp_commit();

#pragma unroll 1
    for (int it = 0; it < nIter; it++) {
        const int cur = it & 1;
        if (it + 1 < nIter) {
            const int nxt = (it + 1) & 1;
            const int k0 = (it + 1) << 4;
            cp16(aDstH0 + nxt * aStageBytes, aSrcH + k0);
            cp16(aDstL0 + nxt * aStageBytes, aSrcL + k0);
            cp16(bDstH0 + nxt * bStageBytes, bSrcH + (size_t)k0 * N);
            cp16(bDstL0 + nxt * bStageBytes, bSrcL + (size_t)k0 * N);
            cp_commit();
            cp_wait1();
        } else {
            cp_wait0();
        }
        __syncthreads();

        const uint32_t aOff = (uint32_t)cur * aStageBytes;
        const uint32_t bOff = (uint32_t)cur * bStageBytes;
        uint32_t bh[4][2], bl[4][2];
#pragma unroll
        for (int nt = 0; nt < 4; nt++) {
            ldsm_x2t(bh[nt][0], bh[nt][1], bBaseH + bOff + nt * 16);
            ldsm_x2t(bl[nt][0], bl[nt][1], bBaseL + bOff + nt * 16);
        }
#pragma unroll
        for (int mt = 0; mt < 4; mt++) {
            uint32_t a0, a1, a2, a3, l0, l1, l2, l3;
            ldsm_x4(a0, a1, a2, a3, aBaseH + aOff + mt * (16 * ASTRIDE * 2));
            ldsm_x4(l0, l1, l2, l3, aBaseL + aOff + mt * (16 * ASTRIDE * 2));
#pragma unroll
            for (int nt = 0; nt < 4; nt++) {
                mma_bf16(acc[mt][nt], a0, a1, a2, a3, bh[nt][0], bh[nt][1]);
                mma_bf16(acc[mt][nt], a0, a1, a2, a3, bl[nt][0], bl[nt][1]);
                mma_bf16(acc[mt][nt], l0, l1, l2, l3, bh[nt][0], bh[nt][1]);
            }
        }
        __syncthreads();
    }

#pragma unroll
    for (int mt = 0; mt < 4; mt++)
#pragma unroll
        for (int nt = 0; nt < 4; nt++) {
            int m = bm + wm * 64 + mt * 16 + (lane >> 2);
            int n = bn + wn * 32 + nt * 8 + ((lane & 3) << 1);
            float b0 = bias ? bias[n] : 0.f;
            float b1 = bias ? bias[n + 1] : 0.f;
            *(float2*)&C[(size_t)m * N + n] = make_float2(acc[mt][nt][0] + b0, acc[mt][nt][1] + b1);
            *(float2*)&C[(size_t)(m + 8) * N + n] = make_float2(acc[mt][nt][2] + b0, acc[mt][nt][3] + b1);
        }
}

// ---------------------------------------------------------------------------
// Adaptive scan — exact R9 version (measured as part of the 2750us run).
// ---------------------------------------------------------------------------
__global__ void __launch_bounds__(128, 1) ascan(
    const float* __restrict__ aWh_f, const float* __restrict__ aWh_b)
{
    const int bid = blockIdx.x;
    const int dir = bid >> 5;
    const int j   = bid & 31;
    const int c0  = j * 4;
    const float* aWh = dir ? aWh_b : aWh_f;
    const float* axg = g_axg[dir];

    __shared__ float aW2[16 * 132];
    __shared__ float ah_sh[32 * 132];

    const int tid = threadIdx.x;
    for (int i = tid; i < 16 * 128; i += 128) {
        int k = i >> 4, c = i & 15;
        int g = c >> 2, hc = c & 3;
        aW2[c * 132 + k] = aWh[k * NAG + (g << 7) + c0 + hc];
    }

    const int b  = tid >> 2;
    const int hc = tid & 3;
    float acst = 0.f;

    for (int t = 0; t < TT; t++) {
        const int p = t & 1;
        if (t > 0 && tid < 32) poll_flag(&g_aflag[dir][tid][0], (unsigned)t);
        __syncthreads();

        if (t == 0) {
            for (int i = tid; i < 32 * 132; i += 128) ah_sh[i] = 0.f;
        } else {
            const float* src = g_ahst[dir][p];
            uint32_t dbase = cvta_s(ah_sh);
            for (int i = tid; i < (BB * AA) / 4; i += 128) {
                int el = i * 4;
                int bb = el >> 7, k = el & 127;
                cp16(dbase + (uint32_t)((bb * 132 + k) * 4), src + el);
            }
            cp_commit();
            cp_wait0();
        }
        __syncthreads();

        const int rowoff = ((b << 8) + t) * NAG + c0 + hc;
        float acc0 = axg[rowoff];
        float acc1 = axg[rowoff + 128];
        float acc2 = axg[rowoff + 256];
        float acc3 = axg[rowoff + 384];

        const float* hp = &ah_sh[b * 132];
        const float* w0 = &aW2[(0 + hc) * 132];
        const float* w1 = &aW2[(4 + hc) * 132];
        const float* w2 = &aW2[(8 + hc) * 132];
        const float* w3 = &aW2[(12 + hc) * 132];
#pragma unroll 8
        for (int k = 0; k < 128; k += 4) {
            float4 h4 = *(const float4*)(hp + k);
            float4 a4 = *(const float4*)(w0 + k);
            float4 b4 = *(const float4*)(w1 + k);
            float4 c4 = *(const float4*)(w2 + k);
            float4 d4 = *(const float4*)(w3 + k);
            acc0 += h4.x * a4.x + h4.y * a4.y + h4.z * a4.z + h4.w * a4.w;
            acc1 += h4.x * b4.x + h4.y * b4.y + h4.z * b4.z + h4.w * b4.w;
            acc2 += h4.x * c4.x + h4.y * c4.y + h4.z * c4.z + h4.w * c4.w;
            acc3 += h4.x * d4.x + h4.y * d4.y + h4.z * d4.z + h4.w * d4.w;
        }

        float ig = sigm(acc0), fg = sigm(acc1), og = sigm(acc3);
        acst = fg * acst + ig * tanhf(acc2);
        float ahv = og * tanhf(acst);

        const int ci = c0 + hc;
        __stcg(&g_ahst[dir][1 - p][(b << 7) + ci], ahv);
        bf16 hh = __float2bfloat16_rn(ahv);
        g_ahT_hi[dir][t][(b << 7) + ci] = hh;
        g_ahT_lo[dir][t][(b << 7) + ci] = __float2bfloat16_rn(ahv - __bfloat162float(hh));

        __syncthreads();
        if (tid == 0) st_release_gpu(&g_aflag[dir][j][0], (unsigned)(t + 1));
    }
}

// ---------------------------------------------------------------------------
// Main scan — exact R9 phase structure (measured 2750us total): Phase A =
// aflag poll -> E stage -> Wz MMAs (hides peer skew), Phase B = mflag poll ->
// h stage -> Wh MMAs -> cell.
// ---------------------------------------------------------------------------
#define WSTRIDE 520
#define ZSTRIDE 136
#define MS_SMEM ((4 * 32 * WSTRIDE) * 2 + (4 * 32 * ZSTRIDE) * 2 + 32 * 36 * 4)

__global__ void __launch_bounds__(256, 1) mscan_mma(
    const float* __restrict__ Wh_f, const float* __restrict__ Wh_b,
    const float* __restrict__ Wz_f, const float* __restrict__ Wz_b,
    float* __restrict__ out)
{
    extern __shared__ __align__(16) char smraw[];
    bf16* Whi_s = (bf16*)smraw;                   // [32][520]
    bf16* Wlo_s = Whi_s + 32 * WSTRIDE;
    bf16* Hhi_s = Wlo_s + 32 * WSTRIDE;           // [32][520]
    bf16* Hlo_s = Hhi_s + 32 * WSTRIDE;
    bf16* Zhi_s = Hlo_s + 32 * WSTRIDE;           // [32][136] Wz slice, [c][k]
    bf16* Zlo_s = Zhi_s + 32 * ZSTRIDE;
    bf16* Ehi_s = Zlo_s + 32 * ZSTRIDE;           // [32][136] ah_t, [b][k]
    bf16* Elo_s = Ehi_s + 32 * ZSTRIDE;
    float* gbuf = (float*)(Elo_s + 32 * ZSTRIDE); // [32][36]

    const int bid = blockIdx.x;
    const int dir = bid >> 6;
    const int j   = bid & 63;
    const int hc0 = j * 8;
    const float* Wh = dir ? Wh_b : Wh_f;
    const float* Wz = dir ? Wz_b : Wz_f;
    const float* xg = g_xg[dir];

    const int tid  = threadIdx.x;
    const int w    = tid >> 5, lane = tid & 31;
    const int mh   = w & 1, g = w >> 1;

    // Prologue: split Wh slice (K=512) and Wz slice (K=128) into smem
    for (int i = tid; i < 32 * 512; i += 256) {
        int c = i & 31, k = i >> 5;
        float wv = Wh[(size_t)k * NG + ((c >> 3) << 9) + hc0 + (c & 7)];
        bf16 h = __float2bfloat16_rn(wv);
        Whi_s[c * WSTRIDE + k] = h;
        Wlo_s[c * WSTRIDE + k] = __float2bfloat16_rn(wv - __bfloat162float(h));
    }
    for (int i = tid; i < 32 * 128; i += 256) {
        int c = i & 31, k = i >> 5;
        float wv = Wz[(size_t)k * NG + ((c >> 3) << 9) + hc0 + (c & 7)];
        bf16 h = __float2bfloat16_rn(wv);
        Zhi_s[c * ZSTRIDE + k] = h;
        Zlo_s[c * ZSTRIDE + k] = __float2bfloat16_rn(wv - __bfloat162float(h));
    }
    __syncthreads();

    const uint32_t aH = cvta_s(Hhi_s) + (uint32_t)(((mh * 16 + (lane & 15)) * WSTRIDE + ((lane >> 4) << 3)) * 2);
    const uint32_t aL = cvta_s(Hlo_s) + (uint32_t)(((mh * 16 + (lane & 15)) * WSTRIDE + ((lane >> 4) << 3)) * 2);
    const uint32_t bH = cvta_s(Whi_s) + (uint32_t)(((g * 8 + (lane & 7)) * WSTRIDE + (lane & 8)) * 2);
    const uint32_t bL = cvta_s(Wlo_s) + (uint32_t)(((g * 8 + (lane & 7)) * WSTRIDE + (lane & 8)) * 2);
    const uint32_t aEH = cvta_s(Ehi_s) + (uint32_t)(((mh * 16 + (lane & 15)) * ZSTRIDE + ((lane >> 4) << 3)) * 2);
    const uint32_t aEL = cvta_s(Elo_s) + (uint32_t)(((mh * 16 + (lane & 15)) * ZSTRIDE + ((lane >> 4) << 3)) * 2);
    const uint32_t bZH = cvta_s(Zhi_s) + (uint32_t)(((g * 8 + (lane & 7)) * ZSTRIDE + (lane & 8)) * 2);
    const uint32_t bZL = cvta_s(Zlo_s) + (uint32_t)(((g * 8 + (lane & 7)) * ZSTRIDE + (lane & 8)) * 2);

    const uint32_t eHiBase = cvta_s(Ehi_s);
    const uint32_t eLoBase = cvta_s(Elo_s);
    const uint32_t hHiBase = cvta_s(Hhi_s);
    const uint32_t hLoBase = cvta_s(Hlo_s);

    // Hoist loop-invariant Wz B fragments into registers (8 k-chunks)
    uint32_t zbh[8][2], zbl[8][2];
#pragma unroll
    for (int c = 0; c < 8; c++) {
        ldsm_x2(zbh[c][0], zbh[c][1], bZH + c * 32);
        ldsm_x2(zbl[c][0], zbl[c][1], bZL + c * 32);
    }

    const int b  = tid >> 3;
    const int hc = tid & 7;
    float cst = 0.f;

    for (int t = 0; t < TT; t++) {
        const int p = t & 1;

        // --- Phase A: ascan-dependent work (peers get time to arrive) ------
        if (tid < 32) poll_flag(&g_aflag[dir][tid][0], (unsigned)(t + 1));
        __syncthreads();
        {
            const bf16* eh = g_ahT_hi[dir][t];
            const bf16* el = g_ahT_lo[dir][t];
            for (int i = tid; i < 512; i += 256) {
                int e = i << 3;
                int bb = e >> 7, k = e & 127;
                uint32_t off = (uint32_t)((bb * ZSTRIDE + k) * 2);
                cp16(eHiBase + off, eh + e);
                cp16(eLoBase + off, el + e);
            }
            cp_commit();
            cp_wait0();
        }
        __syncthreads();

        float c4[4] = {0.f, 0.f, 0.f, 0.f};
#pragma unroll
        for (int c = 0; c < 8; c++) {
            uint32_t a0, a1, a2, a3, l0, l1, l2, l3;
            ldsm_x4(a0, a1, a2, a3, aEH + c * 32);
            ldsm_x4(l0, l1, l2, l3, aEL + c * 32);
            mma_bf16(c4, a0, a1, a2, a3, zbh[c][0], zbh[c][1]);
            mma_bf16(c4, a0, a1, a2, a3, zbl[c][0], zbl[c][1]);
            mma_bf16(c4, l0, l1, l2, l3, zbh[c][0], zbh[c][1]);
        }

        // prefetch xg gate rows (consumed in the cell)
        const float* xr = xg + (size_t)((b << 8) + t) * NG + hc0 + hc;
        float x0 = xr[0], x1 = xr[512], x2 = xr[1024], x3 = xr[1536];

        // --- Phase B: peer-dependent work ---------------------------------
        if (t > 0 && tid < 64) poll_flag(&g_mflag[dir][tid][0], (unsigned)t);
        __syncthreads();

        if (t == 0) {
            uint4 z = make_uint4(0, 0, 0, 0);
            for (int i = tid; i < (32 * WSTRIDE) / 8; i += 256) {
                ((uint4*)Hhi_s)[i] = z;
                ((uint4*)Hlo_s)[i] = z;
            }
        } else {
            const bf16* sh = g_hsth[dir][p];
            const bf16* sl = g_hstl[dir][p];
            for (int i = tid; i < 2048; i += 256) {
                int e = i << 3;
                int bb = e >> 9, k = e & 511;
                uint32_t off = (uint32_t)((bb * WSTRIDE + k) * 2);
                cp16(hHiBase + off, sh + e);
                cp16(hLoBase + off, sl + e);
            }
            cp_commit();
            cp_wait0();
        }
        __syncthreads();

        // h@Wh (K=512, split x3)
#pragma unroll 4
        for (int k0 = 0; k0 < 512; k0 += 16) {
            uint32_t ah0, ah1, ah2, ah3, al0, al1, al2, al3, bh0, bh1, bl0, bl1;
            ldsm_x4(ah0, ah1, ah2, ah3, aH + k0 * 2);
            ldsm_x4(al0, al1, al2, al3, aL + k0 * 2);
            ldsm_x2(bh0, bh1, bH + k0 * 2);
            ldsm_x2(bl0, bl1, bL + k0 * 2);
            mma_bf16(c4, ah0, ah1, ah2, ah3, bh0, bh1);
            mma_bf16(c4, ah0, ah1, ah2, ah3, bl0, bl1);
            mma_bf16(c4, al0, al1, al2, al3, bh0, bh1);
        }

        // scatter fragments to gate buffer
        {
            int m = mh * 16 + (lane >> 2);
            int nc = g * 8 + ((lane & 3) << 1);
            gbuf[m * 36 + nc]     = c4[0];
            gbuf[m * 36 + nc + 1] = c4[1];
            gbuf[(m + 8) * 36 + nc]     = c4[2];
            gbuf[(m + 8) * 36 + nc + 1] = c4[3];
        }
        __syncthreads();

        // LSTM cell; publish h + flag first, out store after
        float hv;
        {
            float gi = gbuf[b * 36 + hc]      + x0;
            float gf = gbuf[b * 36 + 8 + hc]  + x1;
            float gu = gbuf[b * 36 + 16 + hc] + x2;
            float go = gbuf[b * 36 + 24 + hc] + x3;
            cst = sigm(gf) * cst + sigm(gi) * tanhf(gu);
            hv = sigm(go) * tanhf(cst);

            bf16 hh = __float2bfloat16_rn(hv);
            bf16 hl = __float2bfloat16_rn(hv - __bfloat162float(hh));
            int hidx = (b << 9) + hc0 + hc;
            __stcg(&g_hsth[dir][1 - p][hidx], hh);
            __stcg(&g_hstl[dir][1 - p][hidx], hl);
        }
        __syncthreads();
        if (tid == 0) st_release_gpu(&g_mflag[dir][j][0], (unsigned)(t + 1));

        out[(size_t)((b << 8) + t) * 1024 + (dir << 9) + hc0 + hc] = hv;
    }
}

// ---------------------------------------------------------------------------
static cudaStream_t s_side = nullptr;
static cudaEvent_t  s_evA  = nullptr;
static cudaEvent_t  s_evB  = nullptr;

extern "C" void kernel_launch(void* const* d_in, const int* in_sizes, int n_in,
                              void* d_out, int out_size)
{
    const float* x     = (const float*)d_in[0];
    const float* Wx_f  = (const float*)d_in[1];
    const float* Wh_f  = (const float*)d_in[2];
    const float* b_f   = (const float*)d_in[3];
    const float* aWx_f = (const float*)d_in[4];
    const float* aWh_f = (const float*)d_in[5];
    const float* ab_f  = (const float*)d_in[6];
    const float* Wz_f  = (const float*)d_in[7];
    const float* Wx_b  = (const float*)d_in[8];
    const float* Wh_b  = (const float*)d_in[9];
    const float* b_b   = (const float*)d_in[10];
    const float* aWx_b = (const float*)d_in[11];
    const float* aWh_b = (const float*)d_in[12];
    const float* ab_b  = (const float*)d_in[13];
    const float* Wz_b  = (const float*)d_in[14];
    float* out = (float*)d_out;

    if (!s_side) {
        cudaStreamCreateWithFlags(&s_side, cudaStreamNonBlocking);
        cudaEventCreateWithFlags(&s_evA, cudaEventDisableTiming);
        cudaEventCreateWithFlags(&s_evB, cudaEventDisableTiming);
        cudaFuncSetAttribute(mscan_mma, cudaFuncAttributeMaxDynamicSharedMemorySize, MS_SMEM);
    }

    // [1] prep: flag reset + all bf16 splits
    prep<<<1664, 1024>>>(x, Wx_f, Wx_b, aWx_f, aWx_b);

    // [2-3] adaptive x-projections
    gemm_mma<<<dim3(NAG / 128, MROWS / 128), 256>>>(2, ab_f, 2, NAG, DD);
    gemm_mma<<<dim3(NAG / 128, MROWS / 128), 256>>>(3, ab_b, 3, NAG, DD);
    cudaEventRecord(s_evA, 0);

    // [4-5] main x-projections
    gemm_mma<<<dim3(NG / 128, MROWS / 128), 256>>>(0, b_f, 0, NG, DD);
    gemm_mma<<<dim3(NG / 128, MROWS / 128), 256>>>(1, b_b, 1, NG, DD);

    // [6] main scan
    mscan_mma<<<128, 256, MS_SMEM>>>(Wh_f, Wh_b, Wz_f, Wz_b, out);

    // [7] adaptive scan on the side stream (overlaps xg GEMMs + mscan)
    cudaStreamWaitEvent(s_side, s_evA, 0);
    ascan<<<64, 128, 0, s_side>>>(aWh_f, aWh_b);
    cudaEventRecord(s_evB, s_side);

    // join the side branch
    cudaStreamWaitEvent(0, s_evB, 0);
}

// round 13
// speedup vs baseline: 1.1381x; 1.1325x over previous
#include <cuda_runtime.h>
#include <cuda_bf16.h>
#include <cstdint>
#include <math.h>

// ---------------------------------------------------------------------------
// Problem constants
// ---------------------------------------------------------------------------
#define BB   32
#define TT   256
#define DD   512
#define HH   512
#define AA   128
#define MROWS 8192      // B*T
#define NG    2048      // 4H
#define NAG   512       // 4A

typedef __nv_bfloat16 bf16;

// ---------------------------------------------------------------------------
// Static device workspace
// ---------------------------------------------------------------------------
__device__ float g_xg [2][MROWS * NG];    // per dir: x@Wx + b. row = b*T+t
__device__ float g_axg[2][MROWS * NAG];   // per dir: x@aWx + ab. row = b*T+t
__device__ float g_ahst[2][2][BB * AA];   // double-buffered adaptive hidden state
__device__ bf16  g_hsth[2][2][BB * HH];   // double-buffered main hidden (hi)
__device__ bf16  g_hstl[2][2][BB * HH];   // double-buffered main hidden (lo)

// Epoch flags: one 128B-padded slot per CTA
__device__ unsigned g_mflag[2][64][32];   // mscan CTAs
__device__ unsigned g_aflag[2][32][32];   // ascan CTAs

// bf16 hi/lo splits
__device__ bf16 g_Xhi [MROWS * DD],  g_Xlo [MROWS * DD];
__device__ bf16 g_Wxhi[2][DD * NG],  g_Wxlo[2][DD * NG];
__device__ bf16 g_aWxhi[2][DD * NAG], g_aWxlo[2][DD * NAG];

// t-major adaptive hidden stream for mscan consumption: [dir][t][b*128+c]
__device__ bf16 g_ahT_hi[2][TT][BB * AA];
__device__ bf16 g_ahT_lo[2][TT][BB * AA];

__device__ __forceinline__ float sigm(float x) { return 1.f / (1.f + expf(-x)); }

// --- release/acquire primitives -------------------------------------------
__device__ __forceinline__ void st_release_gpu(unsigned* p, unsigned v) {
    asm volatile("st.release.gpu.global.u32 [%0], %1;" :: "l"(p), "r"(v));
}
__device__ __forceinline__ unsigned ld_acquire_gpu(const unsigned* p) {
    unsigned v;
    asm volatile("ld.acquire.gpu.global.u32 %0, [%1];" : "=r"(v) : "l"(p));
    return v;
}
__device__ __forceinline__ void poll_flag(const unsigned* p, unsigned tgt) {
    int s = 0;
    while (ld_acquire_gpu(p) < tgt) {
        if (++s > 16) __nanosleep(40);
    }
}

// --- cp.async (16B, L2-direct) --------------------------------------------
__device__ __forceinline__ void cp16(uint32_t dst, const void* src) {
    asm volatile("cp.async.cg.shared.global [%0], [%1], 16;" :: "r"(dst), "l"(src));
}
__device__ __forceinline__ void cp_commit() {
    asm volatile("cp.async.commit_group;");
}
__device__ __forceinline__ void cp_wait0() {
    asm volatile("cp.async.wait_group 0;" ::: "memory");
}

// ---------------------------------------------------------------------------
// mma.sync helpers (bf16, m16n8k16, fp32 accumulate)
// ---------------------------------------------------------------------------
__device__ __forceinline__ uint32_t cvta_s(const void* p) {
    return (uint32_t)__cvta_generic_to_shared(p);
}
__device__ __forceinline__ void ldsm_x4(uint32_t& r0, uint32_t& r1, uint32_t& r2, uint32_t& r3, uint32_t a) {
    asm volatile("ldmatrix.sync.aligned.m8n8.x4.shared.b16 {%0,%1,%2,%3}, [%4];"
                 : "=r"(r0), "=r"(r1), "=r"(r2), "=r"(r3) : "r"(a));
}
__device__ __forceinline__ void ldsm_x2(uint32_t& r0, uint32_t& r1, uint32_t a) {
    asm volatile("ldmatrix.sync.aligned.m8n8.x2.shared.b16 {%0,%1}, [%2];"
                 : "=r"(r0), "=r"(r1) : "r"(a));
}
__device__ __forceinline__ void ldsm_x2t(uint32_t& r0, uint32_t& r1, uint32_t a) {
    asm volatile("ldmatrix.sync.aligned.m8n8.x2.trans.shared.b16 {%0,%1}, [%2];"
                 : "=r"(r0), "=r"(r1) : "r"(a));
}
__device__ __forceinline__ void mma_bf16(float* c, uint32_t a0, uint32_t a1, uint32_t a2, uint32_t a3,
                                         uint32_t b0, uint32_t b1) {
    asm volatile(
        "mma.sync.aligned.m16n8k16.row.col.f32.bf16.bf16.f32 "
        "{%0,%1,%2,%3}, {%4,%5,%6,%7}, {%8,%9}, {%0,%1,%2,%3};"
        : "+f"(c[0]), "+f"(c[1]), "+f"(c[2]), "+f"(c[3])
        : "r"(a0), "r"(a1), "r"(a2), "r"(a3), "r"(b0), "r"(b1));
}

// ---------------------------------------------------------------------------
// prep: ONE kernel — flag reset + ALL fp32->bf16 hi/lo splits
// ---------------------------------------------------------------------------
#define N_X4   (MROWS * DD / 4)
#define N_WX4  (DD * NG / 4)
#define N_AWX4 (DD * NAG / 4)
#define N_TOT4 (N_X4 + 2 * N_WX4 + 2 * N_AWX4)

__device__ __forceinline__ void split4(const float4* s4, bf16* hi, bf16* lo, int i) {
    float4 v = s4[i];
    bf16 hx = __float2bfloat16_rn(v.x);
    bf16 hy = __float2bfloat16_rn(v.y);
    bf16 hz = __float2bfloat16_rn(v.z);
    bf16 hw = __float2bfloat16_rn(v.w);
    __nv_bfloat162 hp0, hp1, lp0, lp1;
    hp0.x = hx; hp0.y = hy; hp1.x = hz; hp1.y = hw;
    lp0.x = __float2bfloat16_rn(v.x - __bfloat162float(hx));
    lp0.y = __float2bfloat16_rn(v.y - __bfloat162float(hy));
    lp1.x = __float2bfloat16_rn(v.z - __bfloat162float(hz));
    lp1.y = __float2bfloat16_rn(v.w - __bfloat162float(hw));
    ((uint2*)hi)[i] = make_uint2(*(uint32_t*)&hp0, *(uint32_t*)&hp1);
    ((uint2*)lo)[i] = make_uint2(*(uint32_t*)&lp0, *(uint32_t*)&lp1);
}

__global__ void prep(const float* __restrict__ x,
                     const float* __restrict__ Wx_f, const float* __restrict__ Wx_b,
                     const float* __restrict__ aWx_f, const float* __restrict__ aWx_b)
{
    int gid = blockIdx.x * blockDim.x + threadIdx.x;
    if (gid < 2 * 64 * 32) ((unsigned*)g_mflag)[gid] = 0u;
    if (gid < 2 * 32 * 32) ((unsigned*)g_aflag)[gid] = 0u;

    for (int i = gid; i < N_TOT4; i += gridDim.x * blockDim.x) {
        int r = i;
        if (r < N_X4) { split4((const float4*)x, g_Xhi, g_Xlo, r); continue; }
        r -= N_X4;
        if (r < N_WX4) { split4((const float4*)Wx_f, g_Wxhi[0], g_Wxlo[0], r); continue; }
        r -= N_WX4;
        if (r < N_WX4) { split4((const float4*)Wx_b, g_Wxhi[1], g_Wxlo[1], r); continue; }
        r -= N_WX4;
        if (r < N_AWX4) { split4((const float4*)aWx_f, g_aWxhi[0], g_aWxlo[0], r); continue; }
        r -= N_AWX4;
        split4((const float4*)aWx_b, g_aWxhi[1], g_aWxlo[1], r);
    }
}

// ---------------------------------------------------------------------------
// bf16-split GEMM — exact R9 version (single-buffered, streamed A frags).
// This is the variant measured in the 2750us run.
// ---------------------------------------------------------------------------
__global__ void __launch_bounds__(256, 2) gemm_mma(
    int bsel, const float* __restrict__ bias, int csel, int N, int K)
{
    const bf16 *Ahi = g_Xhi, *Alo = g_Xlo;
    const bf16 *Bhi, *Blo;
    float* C;
    switch (bsel) {
        case 0:  Bhi = g_Wxhi[0];  Blo = g_Wxlo[0];  break;
        case 1:  Bhi = g_Wxhi[1];  Blo = g_Wxlo[1];  break;
        case 2:  Bhi = g_aWxhi[0]; Blo = g_aWxlo[0]; break;
        default: Bhi = g_aWxhi[1]; Blo = g_aWxlo[1]; break;
    }
    switch (csel) {
        case 0:  C = g_xg[0];  break;
        case 1:  C = g_xg[1];  break;
        case 2:  C = g_axg[0]; break;
        default: C = g_axg[1]; break;
    }

    __shared__ __align__(16) bf16 sAh[128 * 24], sAl[128 * 24];
    __shared__ __align__(16) bf16 sBh[16 * 136], sBl[16 * 136];

    const int tid  = threadIdx.x;
    const int w    = tid >> 5, lane = tid & 31;
    const int wm   = w & 1,    wn   = w >> 1;
    const int bm   = blockIdx.y * 128;
    const int bn   = blockIdx.x * 128;

    const int arow = tid >> 1, ahalf = tid & 1;
    const int brow = tid >> 4, bseg  = tid & 15;

    float acc[4][4][4];
#pragma unroll
    for (int i = 0; i < 4; i++)
#pragma unroll
        for (int j = 0; j < 4; j++) {
            acc[i][j][0] = 0.f; acc[i][j][1] = 0.f; acc[i][j][2] = 0.f; acc[i][j][3] = 0.f;
        }

    const uint32_t aBaseH = cvta_s(sAh) + (uint32_t)(((wm * 64 + (lane & 15)) * 24 + ((lane >> 4) << 3)) * 2);
    const uint32_t aBaseL = cvta_s(sAl) + (uint32_t)(((wm * 64 + (lane & 15)) * 24 + ((lane >> 4) << 3)) * 2);
    const uint32_t bBaseH = cvta_s(sBh) + (uint32_t)((((lane & 15)) * 136 + wn * 32) * 2);
    const uint32_t bBaseL = cvta_s(sBl) + (uint32_t)((((lane & 15)) * 136 + wn * 32) * 2);

#pragma unroll 1
    for (int k0 = 0; k0 < K; k0 += 16) {
        *(uint4*)&sAh[arow * 24 + ahalf * 8] = *(const uint4*)&Ahi[(size_t)(bm + arow) * K + k0 + ahalf * 8];
        *(uint4*)&sAl[arow * 24 + ahalf * 8] = *(const uint4*)&Alo[(size_t)(bm + arow) * K + k0 + ahalf * 8];
        *(uint4*)&sBh[brow * 136 + bseg * 8] = *(const uint4*)&Bhi[(size_t)(k0 + brow) * N + bn + bseg * 8];
        *(uint4*)&sBl[brow * 136 + bseg * 8] = *(const uint4*)&Blo[(size_t)(k0 + brow) * N + bn + bseg * 8];
        __syncthreads();

        uint32_t bh[4][2], bl[4][2];
#pragma unroll
        for (int nt = 0; nt < 4; nt++) {
            ldsm_x2t(bh[nt][0], bh[nt][1], bBaseH + nt * 16);
            ldsm_x2t(bl[nt][0], bl[nt][1], bBaseL + nt * 16);
        }
#pragma unroll
        for (int mt = 0; mt < 4; mt++) {
            uint32_t a0, a1, a2, a3, l0, l1, l2, l3;
            ldsm_x4(a0, a1, a2, a3, aBaseH + mt * 768);
            ldsm_x4(l0, l1, l2, l3, aBaseL + mt * 768);
#pragma unroll
            for (int nt = 0; nt < 4; nt++) {
                mma_bf16(acc[mt][nt], a0, a1, a2, a3, bh[nt][0], bh[nt][1]);
                mma_bf16(acc[mt][nt], a0, a1, a2, a3, bl[nt][0], bl[nt][1]);
                mma_bf16(acc[mt][nt], l0, l1, l2, l3, bh[nt][0], bh[nt][1]);
            }
        }
        __syncthreads();
    }

#pragma unroll
    for (int mt = 0; mt < 4; mt++)
#pragma unroll
        for (int nt = 0; nt < 4; nt++) {
            int m = bm + wm * 64 + mt * 16 + (lane >> 2);
            int n = bn + wn * 32 + nt * 8 + ((lane & 3) << 1);
            float b0 = bias ? bias[n] : 0.f;
            float b1 = bias ? bias[n + 1] : 0.f;
            *(float2*)&C[(size_t)m * N + n] = make_float2(acc[mt][nt][0] + b0, acc[mt][nt][1] + b1);
            *(float2*)&C[(size_t)(m + 8) * N + n] = make_float2(acc[mt][nt][2] + b0, acc[mt][nt][3] + b1);
        }
}

// ---------------------------------------------------------------------------
// Adaptive scan — exact R9 version.
// ---------------------------------------------------------------------------
__global__ void __launch_bounds__(128, 1) ascan(
    const float* __restrict__ aWh_f, const float* __restrict__ aWh_b)
{
    const int bid = blockIdx.x;
    const int dir = bid >> 5;
    const int j   = bid & 31;
    const int c0  = j * 4;
    const float* aWh = dir ? aWh_b : aWh_f;
    const float* axg = g_axg[dir];

    __shared__ float aW2[16 * 132];
    __shared__ float ah_sh[32 * 132];

    const int tid = threadIdx.x;
    for (int i = tid; i < 16 * 128; i += 128) {
        int k = i >> 4, c = i & 15;
        int g = c >> 2, hc = c & 3;
        aW2[c * 132 + k] = aWh[k * NAG + (g << 7) + c0 + hc];
    }

    const int b  = tid >> 2;
    const int hc = tid & 3;
    float acst = 0.f;

    for (int t = 0; t < TT; t++) {
        const int p = t & 1;
        if (t > 0 && tid < 32) poll_flag(&g_aflag[dir][tid][0], (unsigned)t);
        __syncthreads();

        if (t == 0) {
            for (int i = tid; i < 32 * 132; i += 128) ah_sh[i] = 0.f;
        } else {
            const float* src = g_ahst[dir][p];
            uint32_t dbase = cvta_s(ah_sh);
            for (int i = tid; i < (BB * AA) / 4; i += 128) {
                int el = i * 4;
                int bb = el >> 7, k = el & 127;
                cp16(dbase + (uint32_t)((bb * 132 + k) * 4), src + el);
            }
            cp_commit();
            cp_wait0();
        }
        __syncthreads();

        const int rowoff = ((b << 8) + t) * NAG + c0 + hc;
        float acc0 = axg[rowoff];
        float acc1 = axg[rowoff + 128];
        float acc2 = axg[rowoff + 256];
        float acc3 = axg[rowoff + 384];

        const float* hp = &ah_sh[b * 132];
        const float* w0 = &aW2[(0 + hc) * 132];
        const float* w1 = &aW2[(4 + hc) * 132];
        const float* w2 = &aW2[(8 + hc) * 132];
        const float* w3 = &aW2[(12 + hc) * 132];
#pragma unroll 8
        for (int k = 0; k < 128; k += 4) {
            float4 h4 = *(const float4*)(hp + k);
            float4 a4 = *(const float4*)(w0 + k);
            float4 b4 = *(const float4*)(w1 + k);
            float4 c4 = *(const float4*)(w2 + k);
            float4 d4 = *(const float4*)(w3 + k);
            acc0 += h4.x * a4.x + h4.y * a4.y + h4.z * a4.z + h4.w * a4.w;
            acc1 += h4.x * b4.x + h4.y * b4.y + h4.z * b4.z + h4.w * b4.w;
            acc2 += h4.x * c4.x + h4.y * c4.y + h4.z * c4.z + h4.w * c4.w;
            acc3 += h4.x * d4.x + h4.y * d4.y + h4.z * d4.z + h4.w * d4.w;
        }

        float ig = sigm(acc0), fg = sigm(acc1), og = sigm(acc3);
        acst = fg * acst + ig * tanhf(acc2);
        float ahv = og * tanhf(acst);

        const int ci = c0 + hc;
        __stcg(&g_ahst[dir][1 - p][(b << 7) + ci], ahv);
        bf16 hh = __float2bfloat16_rn(ahv);
        g_ahT_hi[dir][t][(b << 7) + ci] = hh;
        g_ahT_lo[dir][t][(b << 7) + ci] = __float2bfloat16_rn(ahv - __bfloat162float(hh));

        __syncthreads();
        if (tid == 0) st_release_gpu(&g_aflag[dir][j][0], (unsigned)(t + 1));
    }
}

// ---------------------------------------------------------------------------
// Main scan — exact R9 phase structure.
// ---------------------------------------------------------------------------
#define WSTRIDE 520
#define ZSTRIDE 136
#define MS_SMEM ((4 * 32 * WSTRIDE) * 2 + (4 * 32 * ZSTRIDE) * 2 + 32 * 36 * 4)

__global__ void __launch_bounds__(256, 1) mscan_mma(
    const float* __restrict__ Wh_f, const float* __restrict__ Wh_b,
    const float* __restrict__ Wz_f, const float* __restrict__ Wz_b,
    float* __restrict__ out)
{
    extern __shared__ __align__(16) char smraw[];
    bf16* Whi_s = (bf16*)smraw;                   // [32][520]
    bf16* Wlo_s = Whi_s + 32 * WSTRIDE;
    bf16* Hhi_s = Wlo_s + 32 * WSTRIDE;           // [32][520]
    bf16* Hlo_s = Hhi_s + 32 * WSTRIDE;
    bf16* Zhi_s = Hlo_s + 32 * WSTRIDE;           // [32][136] Wz slice, [c][k]
    bf16* Zlo_s = Zhi_s + 32 * ZSTRIDE;
    bf16* Ehi_s = Zlo_s + 32 * ZSTRIDE;           // [32][136] ah_t, [b][k]
    bf16* Elo_s = Ehi_s + 32 * ZSTRIDE;
    float* gbuf = (float*)(Elo_s + 32 * ZSTRIDE); // [32][36]

    const int bid = blockIdx.x;
    const int dir = bid >> 6;
    const int j   = bid & 63;
    const int hc0 = j * 8;
    const float* Wh = dir ? Wh_b : Wh_f;
    const float* Wz = dir ? Wz_b : Wz_f;
    const float* xg = g_xg[dir];

    const int tid  = threadIdx.x;
    const int w    = tid >> 5, lane = tid & 31;
    const int mh   = w & 1, g = w >> 1;

    for (int i = tid; i < 32 * 512; i += 256) {
        int c = i & 31, k = i >> 5;
        float wv = Wh[(size_t)k * NG + ((c >> 3) << 9) + hc0 + (c & 7)];
        bf16 h = __float2bfloat16_rn(wv);
        Whi_s[c * WSTRIDE + k] = h;
        Wlo_s[c * WSTRIDE + k] = __float2bfloat16_rn(wv - __bfloat162float(h));
    }
    for (int i = tid; i < 32 * 128; i += 256) {
        int c = i & 31, k = i >> 5;
        float wv = Wz[(size_t)k * NG + ((c >> 3) << 9) + hc0 + (c & 7)];
        bf16 h = __float2bfloat16_rn(wv);
        Zhi_s[c * ZSTRIDE + k] = h;
        Zlo_s[c * ZSTRIDE + k] = __float2bfloat16_rn(wv - __bfloat162float(h));
    }
    __syncthreads();

    const uint32_t aH = cvta_s(Hhi_s) + (uint32_t)(((mh * 16 + (lane & 15)) * WSTRIDE + ((lane >> 4) << 3)) * 2);
    const uint32_t aL = cvta_s(Hlo_s) + (uint32_t)(((mh * 16 + (lane & 15)) * WSTRIDE + ((lane >> 4) << 3)) * 2);
    const uint32_t bH = cvta_s(Whi_s) + (uint32_t)(((g * 8 + (lane & 7)) * WSTRIDE + (lane & 8)) * 2);
    const uint32_t bL = cvta_s(Wlo_s) + (uint32_t)(((g * 8 + (lane & 7)) * WSTRIDE + (lane & 8)) * 2);
    const uint32_t aEH = cvta_s(Ehi_s) + (uint32_t)(((mh * 16 + (lane & 15)) * ZSTRIDE + ((lane >> 4) << 3)) * 2);
    const uint32_t aEL = cvta_s(Elo_s) + (uint32_t)(((mh * 16 + (lane & 15)) * ZSTRIDE + ((lane >> 4) << 3)) * 2);
    const uint32_t bZH = cvta_s(Zhi_s) + (uint32_t)(((g * 8 + (lane & 7)) * ZSTRIDE + (lane & 8)) * 2);
    const uint32_t bZL = cvta_s(Zlo_s) + (uint32_t)(((g * 8 + (lane & 7)) * ZSTRIDE + (lane & 8)) * 2);

    const uint32_t eHiBase = cvta_s(Ehi_s);
    const uint32_t eLoBase = cvta_s(Elo_s);
    const uint32_t hHiBase = cvta_s(Hhi_s);
    const uint32_t hLoBase = cvta_s(Hlo_s);

    uint32_t zbh[8][2], zbl[8][2];
#pragma unroll
    for (int c = 0; c < 8; c++) {
        ldsm_x2(zbh[c][0], zbh[c][1], bZH + c * 32);
        ldsm_x2(zbl[c][0], zbl[c][1], bZL + c * 32);
    }

    const int b  = tid >> 3;
    const int hc = tid & 7;
    float cst = 0.f;

    for (int t = 0; t < TT; t++) {
        const int p = t & 1;

        // --- Phase A: ascan-dependent work (peers get time to arrive) ------
        if (tid < 32) poll_flag(&g_aflag[dir][tid][0], (unsigned)(t + 1));
        __syncthreads();
        {
            const bf16* eh = g_ahT_hi[dir][t];
            const bf16* el = g_ahT_lo[dir][t];
            for (int i = tid; i < 512; i += 256) {
                int e = i << 3;
                int bb = e >> 7, k = e & 127;
                uint32_t off = (uint32_t)((bb * ZSTRIDE + k) * 2);
                cp16(eHiBase + off, eh + e);
                cp16(eLoBase + off, el + e);
            }
            cp_commit();
            cp_wait0();
        }
        __syncthreads();

        float c4[4] = {0.f, 0.f, 0.f, 0.f};
#pragma unroll
        for (int c = 0; c < 8; c++) {
            uint32_t a0, a1, a2, a3, l0, l1, l2, l3;
            ldsm_x4(a0, a1, a2, a3, aEH + c * 32);
            ldsm_x4(l0, l1, l2, l3, aEL + c * 32);
            mma_bf16(c4, a0, a1, a2, a3, zbh[c][0], zbh[c][1]);
            mma_bf16(c4, a0, a1, a2, a3, zbl[c][0], zbl[c][1]);
            mma_bf16(c4, l0, l1, l2, l3, zbh[c][0], zbh[c][1]);
        }

        const float* xr = xg + (size_t)((b << 8) + t) * NG + hc0 + hc;
        float x0 = xr[0], x1 = xr[512], x2 = xr[1024], x3 = xr[1536];

        // --- Phase B: peer-dependent work ---------------------------------
        if (t > 0 && tid < 64) poll_flag(&g_mflag[dir][tid][0], (unsigned)t);
        __syncthreads();

        if (t == 0) {
            uint4 z = make_uint4(0, 0, 0, 0);
            for (int i = tid; i < (32 * WSTRIDE) / 8; i += 256) {
                ((uint4*)Hhi_s)[i] = z;
                ((uint4*)Hlo_s)[i] = z;
            }
        } else {
            const bf16* sh = g_hsth[dir][p];
            const bf16* sl = g_hstl[dir][p];
            for (int i = tid; i < 2048; i += 256) {
                int e = i << 3;
                int bb = e >> 9, k = e & 511;
                uint32_t off = (uint32_t)((bb * WSTRIDE + k) * 2);
                cp16(hHiBase + off, sh + e);
                cp16(hLoBase + off, sl + e);
            }
            cp_commit();
            cp_wait0();
        }
        __syncthreads();

#pragma unroll 4
        for (int k0 = 0; k0 < 512; k0 += 16) {
            uint32_t ah0, ah1, ah2, ah3, al0, al1, al2, al3, bh0, bh1, bl0, bl1;
            ldsm_x4(ah0, ah1, ah2, ah3, aH + k0 * 2);
            ldsm_x4(al0, al1, al2, al3, aL + k0 * 2);
            ldsm_x2(bh0, bh1, bH + k0 * 2);
            ldsm_x2(bl0, bl1, bL + k0 * 2);
            mma_bf16(c4, ah0, ah1, ah2, ah3, bh0, bh1);
            mma_bf16(c4, ah0, ah1, ah2, ah3, bl0, bl1);
            mma_bf16(c4, al0, al1, al2, al3, bh0, bh1);
        }

        {
            int m = mh * 16 + (lane >> 2);
            int nc = g * 8 + ((lane & 3) << 1);
            gbuf[m * 36 + nc]     = c4[0];
            gbuf[m * 36 + nc + 1] = c4[1];
            gbuf[(m + 8) * 36 + nc]     = c4[2];
            gbuf[(m + 8) * 36 + nc + 1] = c4[3];
        }
        __syncthreads();

        float hv;
        {
            float gi = gbuf[b * 36 + hc]      + x0;
            float gf = gbuf[b * 36 + 8 + hc]  + x1;
            float gu = gbuf[b * 36 + 16 + hc] + x2;
            float go = gbuf[b * 36 + 24 + hc] + x3;
            cst = sigm(gf) * cst + sigm(gi) * tanhf(gu);
            hv = sigm(go) * tanhf(cst);

            bf16 hh = __float2bfloat16_rn(hv);
            bf16 hl = __float2bfloat16_rn(hv - __bfloat162float(hh));
            int hidx = (b << 9) + hc0 + hc;
            __stcg(&g_hsth[dir][1 - p][hidx], hh);
            __stcg(&g_hstl[dir][1 - p][hidx], hl);
        }
        __syncthreads();
        if (tid == 0) st_release_gpu(&g_mflag[dir][j][0], (unsigned)(t + 1));

        __stcg(&out[(size_t)((b << 8) + t) * 1024 + (dir << 9) + hc0 + hc], hv);
    }
}

// ---------------------------------------------------------------------------
static cudaStream_t s_side = nullptr;
static cudaEvent_t  s_evA  = nullptr;
static cudaEvent_t  s_evB  = nullptr;

extern "C" void kernel_launch(void* const* d_in, const int* in_sizes, int n_in,
                              void* d_out, int out_size)
{
    const float* x     = (const float*)d_in[0];
    const float* Wx_f  = (const float*)d_in[1];
    const float* Wh_f  = (const float*)d_in[2];
    const float* b_f   = (const float*)d_in[3];
    const float* aWx_f = (const float*)d_in[4];
    const float* aWh_f = (const float*)d_in[5];
    const float* ab_f  = (const float*)d_in[6];
    const float* Wz_f  = (const float*)d_in[7];
    const float* Wx_b  = (const float*)d_in[8];
    const float* Wh_b  = (const float*)d_in[9];
    const float* b_b   = (const float*)d_in[10];
    const float* aWx_b = (const float*)d_in[11];
    const float* aWh_b = (const float*)d_in[12];
    const float* ab_b  = (const float*)d_in[13];
    const float* Wz_b  = (const float*)d_in[14];
    float* out = (float*)d_out;

    if (!s_side) {
        cudaStreamCreateWithFlags(&s_side, cudaStreamNonBlocking);
        cudaEventCreateWithFlags(&s_evA, cudaEventDisableTiming);
        cudaEventCreateWithFlags(&s_evB, cudaEventDisableTiming);
        cudaFuncSetAttribute(mscan_mma, cudaFuncAttributeMaxDynamicSharedMemorySize, MS_SMEM);
    }

    // [1] prep: flag reset + all bf16 splits
    prep<<<1664, 1024>>>(x, Wx_f, Wx_b, aWx_f, aWx_b);

    // [2-3] adaptive x-projections
    gemm_mma<<<dim3(NAG / 128, MROWS / 128), 256>>>(2, ab_f, 2, NAG, DD);
    gemm_mma<<<dim3(NAG / 128, MROWS / 128), 256>>>(3, ab_b, 3, NAG, DD);
    cudaEventRecord(s_evA, 0);

    // [4-5] main x-projections
    gemm_mma<<<dim3(NG / 128, MROWS / 128), 256>>>(0, b_f, 0, NG, DD);
    gemm_mma<<<dim3(NG / 128, MROWS / 128), 256>>>(1, b_b, 1, NG, DD);

    // [6] main scan
    mscan_mma<<<128, 256, MS_SMEM>>>(Wh_f, Wh_b, Wz_f, Wz_b, out);

    // [7] adaptive scan on the side stream (overlaps xg GEMMs + mscan)
    cudaStreamWaitEvent(s_side, s_evA, 0);
    ascan<<<64, 128, 0, s_side>>>(aWh_f, aWh_b);
    cudaEventRecord(s_evB, s_side);

    // join the side branch
    cudaStreamWaitEvent(0, s_evB, 0);
}

// round 14
// speedup vs baseline: 1.1473x; 1.0080x over previous
#include <cuda_runtime.h>
#include <cuda_bf16.h>
#include <cstdint>
#include <math.h>

// ---------------------------------------------------------------------------
// Problem constants
// ---------------------------------------------------------------------------
#define BB   32
#define TT   256
#define DD   512
#define HH   512
#define AA   128
#define MROWS 8192      // B*T
#define NG    2048      // 4H
#define NAG   512       // 4A

typedef __nv_bfloat16 bf16;

// ---------------------------------------------------------------------------
// Static device workspace
// ---------------------------------------------------------------------------
__device__ float g_xg [2][MROWS * NG];    // per dir: x@Wx + b. row = b*T+t
__device__ float g_axg[2][MROWS * NAG];   // per dir: x@aWx + ab. row = b*T+t
__device__ float g_ahst[2][2][BB * AA];   // double-buffered adaptive hidden state
__device__ bf16  g_hsth[2][2][BB * HH];   // double-buffered main hidden (hi)
__device__ bf16  g_hstl[2][2][BB * HH];   // double-buffered main hidden (lo)

// Epoch flags: one 128B-padded slot per CTA
__device__ unsigned g_mflag[2][64][32];   // mscan CTAs
__device__ unsigned g_aflag[2][32][32];   // ascan CTAs

// bf16 hi/lo splits
__device__ bf16 g_Xhi [MROWS * DD],  g_Xlo [MROWS * DD];
__device__ bf16 g_Wxhi[2][DD * NG],  g_Wxlo[2][DD * NG];
__device__ bf16 g_aWxhi[2][DD * NAG], g_aWxlo[2][DD * NAG];

// t-major adaptive hidden stream for mscan consumption: [dir][t][b*128+c]
__device__ bf16 g_ahT_hi[2][TT][BB * AA];
__device__ bf16 g_ahT_lo[2][TT][BB * AA];

__device__ __forceinline__ float sigm(float x) { return 1.f / (1.f + expf(-x)); }

// --- release/acquire primitives -------------------------------------------
__device__ __forceinline__ void st_release_gpu(unsigned* p, unsigned v) {
    asm volatile("st.release.gpu.global.u32 [%0], %1;" :: "l"(p), "r"(v));
}
__device__ __forceinline__ unsigned ld_acquire_gpu(const unsigned* p) {
    unsigned v;
    asm volatile("ld.acquire.gpu.global.u32 %0, [%1];" : "=r"(v) : "l"(p));
    return v;
}
__device__ __forceinline__ void poll_flag(const unsigned* p, unsigned tgt) {
    int s = 0;
    while (ld_acquire_gpu(p) < tgt) {
        if (++s > 16) __nanosleep(40);
    }
}

// --- cp.async (16B, L2-direct) --------------------------------------------
__device__ __forceinline__ void cp16(uint32_t dst, const void* src) {
    asm volatile("cp.async.cg.shared.global [%0], [%1], 16;" :: "r"(dst), "l"(src));
}
__device__ __forceinline__ void cp_commit() {
    asm volatile("cp.async.commit_group;");
}
__device__ __forceinline__ void cp_wait0() {
    asm volatile("cp.async.wait_group 0;" ::: "memory");
}

// ---------------------------------------------------------------------------
// mma.sync helpers (bf16, m16n8k16, fp32 accumulate)
// ---------------------------------------------------------------------------
__device__ __forceinline__ uint32_t cvta_s(const void* p) {
    return (uint32_t)__cvta_generic_to_shared(p);
}
__device__ __forceinline__ void ldsm_x4(uint32_t& r0, uint32_t& r1, uint32_t& r2, uint32_t& r3, uint32_t a) {
    asm volatile("ldmatrix.sync.aligned.m8n8.x4.shared.b16 {%0,%1,%2,%3}, [%4];"
                 : "=r"(r0), "=r"(r1), "=r"(r2), "=r"(r3) : "r"(a));
}
__device__ __forceinline__ void ldsm_x2(uint32_t& r0, uint32_t& r1, uint32_t a) {
    asm volatile("ldmatrix.sync.aligned.m8n8.x2.shared.b16 {%0,%1}, [%2];"
                 : "=r"(r0), "=r"(r1) : "r"(a));
}
__device__ __forceinline__ void ldsm_x2t(uint32_t& r0, uint32_t& r1, uint32_t a) {
    asm volatile("ldmatrix.sync.aligned.m8n8.x2.trans.shared.b16 {%0,%1}, [%2];"
                 : "=r"(r0), "=r"(r1) : "r"(a));
}
__device__ __forceinline__ void mma_bf16(float* c, uint32_t a0, uint32_t a1, uint32_t a2, uint32_t a3,
                                         uint32_t b0, uint32_t b1) {
    asm volatile(
        "mma.sync.aligned.m16n8k16.row.col.f32.bf16.bf16.f32 "
        "{%0,%1,%2,%3}, {%4,%5,%6,%7}, {%8,%9}, {%0,%1,%2,%3};"
        : "+f"(c[0]), "+f"(c[1]), "+f"(c[2]), "+f"(c[3])
        : "r"(a0), "r"(a1), "r"(a2), "r"(a3), "r"(b0), "r"(b1));
}

// ---------------------------------------------------------------------------
// prep: ONE kernel — flag reset + ALL fp32->bf16 hi/lo splits
// ---------------------------------------------------------------------------
#define N_X4   (MROWS * DD / 4)
#define N_WX4  (DD * NG / 4)
#define N_AWX4 (DD * NAG / 4)
#define N_TOT4 (N_X4 + 2 * N_WX4 + 2 * N_AWX4)

__device__ __forceinline__ void split4(const float4* s4, bf16* hi, bf16* lo, int i) {
    float4 v = s4[i];
    bf16 hx = __float2bfloat16_rn(v.x);
    bf16 hy = __float2bfloat16_rn(v.y);
    bf16 hz = __float2bfloat16_rn(v.z);
    bf16 hw = __float2bfloat16_rn(v.w);
    __nv_bfloat162 hp0, hp1, lp0, lp1;
    hp0.x = hx; hp0.y = hy; hp1.x = hz; hp1.y = hw;
    lp0.x = __float2bfloat16_rn(v.x - __bfloat162float(hx));
    lp0.y = __float2bfloat16_rn(v.y - __bfloat162float(hy));
    lp1.x = __float2bfloat16_rn(v.z - __bfloat162float(hz));
    lp1.y = __float2bfloat16_rn(v.w - __bfloat162float(hw));
    ((uint2*)hi)[i] = make_uint2(*(uint32_t*)&hp0, *(uint32_t*)&hp1);
    ((uint2*)lo)[i] = make_uint2(*(uint32_t*)&lp0, *(uint32_t*)&lp1);
}

__global__ void prep(const float* __restrict__ x,
                     const float* __restrict__ Wx_f, const float* __restrict__ Wx_b,
                     const float* __restrict__ aWx_f, const float* __restrict__ aWx_b)
{
    int gid = blockIdx.x * blockDim.x + threadIdx.x;
    if (gid < 2 * 64 * 32) ((unsigned*)g_mflag)[gid] = 0u;
    if (gid < 2 * 32 * 32) ((unsigned*)g_aflag)[gid] = 0u;

    for (int i = gid; i < N_TOT4; i += gridDim.x * blockDim.x) {
        int r = i;
        if (r < N_X4) { split4((const float4*)x, g_Xhi, g_Xlo, r); continue; }
        r -= N_X4;
        if (r < N_WX4) { split4((const float4*)Wx_f, g_Wxhi[0], g_Wxlo[0], r); continue; }
        r -= N_WX4;
        if (r < N_WX4) { split4((const float4*)Wx_b, g_Wxhi[1], g_Wxlo[1], r); continue; }
        r -= N_WX4;
        if (r < N_AWX4) { split4((const float4*)aWx_f, g_aWxhi[0], g_aWxlo[0], r); continue; }
        r -= N_AWX4;
        split4((const float4*)aWx_b, g_aWxhi[1], g_aWxlo[1], r);
    }
}

// ---------------------------------------------------------------------------
// bf16-split GEMM — exact R9/R13 version (the 2750us-run variant). FROZEN.
// ---------------------------------------------------------------------------
__global__ void __launch_bounds__(256, 2) gemm_mma(
    int bsel, const float* __restrict__ bias, int csel, int N, int K)
{
    const bf16 *Ahi = g_Xhi, *Alo = g_Xlo;
    const bf16 *Bhi, *Blo;
    float* C;
    switch (bsel) {
        case 0:  Bhi = g_Wxhi[0];  Blo = g_Wxlo[0];  break;
        case 1:  Bhi = g_Wxhi[1];  Blo = g_Wxlo[1];  break;
        case 2:  Bhi = g_aWxhi[0]; Blo = g_aWxlo[0]; break;
        default: Bhi = g_aWxhi[1]; Blo = g_aWxlo[1]; break;
    }
    switch (csel) {
        case 0:  C = g_xg[0];  break;
        case 1:  C = g_xg[1];  break;
        case 2:  C = g_axg[0]; break;
        default: C = g_axg[1]; break;
    }

    __shared__ __align__(16) bf16 sAh[128 * 24], sAl[128 * 24];
    __shared__ __align__(16) bf16 sBh[16 * 136], sBl[16 * 136];

    const int tid  = threadIdx.x;
    const int w    = tid >> 5, lane = tid & 31;
    const int wm   = w & 1,    wn   = w >> 1;
    const int bm   = blockIdx.y * 128;
    const int bn   = blockIdx.x * 128;

    const int arow = tid >> 1, ahalf = tid & 1;
    const int brow = tid >> 4, bseg  = tid & 15;

    float acc[4][4][4];
#pragma unroll
    for (int i = 0; i < 4; i++)
#pragma unroll
        for (int j = 0; j < 4; j++) {
            acc[i][j][0] = 0.f; acc[i][j][1] = 0.f; acc[i][j][2] = 0.f; acc[i][j][3] = 0.f;
        }

    const uint32_t aBaseH = cvta_s(sAh) + (uint32_t)(((wm * 64 + (lane & 15)) * 24 + ((lane >> 4) << 3)) * 2);
    const uint32_t aBaseL = cvta_s(sAl) + (uint32_t)(((wm * 64 + (lane & 15)) * 24 + ((lane >> 4) << 3)) * 2);
    const uint32_t bBaseH = cvta_s(sBh) + (uint32_t)((((lane & 15)) * 136 + wn * 32) * 2);
    const uint32_t bBaseL = cvta_s(sBl) + (uint32_t)((((lane & 15)) * 136 + wn * 32) * 2);

#pragma unroll 1
    for (int k0 = 0; k0 < K; k0 += 16) {
        *(uint4*)&sAh[arow * 24 + ahalf * 8] = *(const uint4*)&Ahi[(size_t)(bm + arow) * K + k0 + ahalf * 8];
        *(uint4*)&sAl[arow * 24 + ahalf * 8] = *(const uint4*)&Alo[(size_t)(bm + arow) * K + k0 + ahalf * 8];
        *(uint4*)&sBh[brow * 136 + bseg * 8] = *(const uint4*)&Bhi[(size_t)(k0 + brow) * N + bn + bseg * 8];
        *(uint4*)&sBl[brow * 136 + bseg * 8] = *(const uint4*)&Blo[(size_t)(k0 + brow) * N + bn + bseg * 8];
        __syncthreads();

        uint32_t bh[4][2], bl[4][2];
#pragma unroll
        for (int nt = 0; nt < 4; nt++) {
            ldsm_x2t(bh[nt][0], bh[nt][1], bBaseH + nt * 16);
            ldsm_x2t(bl[nt][0], bl[nt][1], bBaseL + nt * 16);
        }
#pragma unroll
        for (int mt = 0; mt < 4; mt++) {
            uint32_t a0, a1, a2, a3, l0, l1, l2, l3;
            ldsm_x4(a0, a1, a2, a3, aBaseH + mt * 768);
            ldsm_x4(l0, l1, l2, l3, aBaseL + mt * 768);
#pragma unroll
            for (int nt = 0; nt < 4; nt++) {
                mma_bf16(acc[mt][nt], a0, a1, a2, a3, bh[nt][0], bh[nt][1]);
                mma_bf16(acc[mt][nt], a0, a1, a2, a3, bl[nt][0], bl[nt][1]);
                mma_bf16(acc[mt][nt], l0, l1, l2, l3, bh[nt][0], bh[nt][1]);
            }
        }
        __syncthreads();
    }

#pragma unroll
    for (int mt = 0; mt < 4; mt++)
#pragma unroll
        for (int nt = 0; nt < 4; nt++) {
            int m = bm + wm * 64 + mt * 16 + (lane >> 2);
            int n = bn + wn * 32 + nt * 8 + ((lane & 3) << 1);
            float b0 = bias ? bias[n] : 0.f;
            float b1 = bias ? bias[n + 1] : 0.f;
            *(float2*)&C[(size_t)m * N + n] = make_float2(acc[mt][nt][0] + b0, acc[mt][nt][1] + b1);
            *(float2*)&C[(size_t)(m + 8) * N + n] = make_float2(acc[mt][nt][2] + b0, acc[mt][nt][3] + b1);
        }
}

// ---------------------------------------------------------------------------
// Adaptive scan — exact R9 version. FROZEN.
// ---------------------------------------------------------------------------
__global__ void __launch_bounds__(128, 1) ascan(
    const float* __restrict__ aWh_f, const float* __restrict__ aWh_b)
{
    const int bid = blockIdx.x;
    const int dir = bid >> 5;
    const int j   = bid & 31;
    const int c0  = j * 4;
    const float* aWh = dir ? aWh_b : aWh_f;
    const float* axg = g_axg[dir];

    __shared__ float aW2[16 * 132];
    __shared__ float ah_sh[32 * 132];

    const int tid = threadIdx.x;
    for (int i = tid; i < 16 * 128; i += 128) {
        int k = i >> 4, c = i & 15;
        int g = c >> 2, hc = c & 3;
        aW2[c * 132 + k] = aWh[k * NAG + (g << 7) + c0 + hc];
    }

    const int b  = tid >> 2;
    const int hc = tid & 3;
    float acst = 0.f;

    for (int t = 0; t < TT; t++) {
        const int p = t & 1;
        if (t > 0 && tid < 32) poll_flag(&g_aflag[dir][tid][0], (unsigned)t);
        __syncthreads();

        if (t == 0) {
            for (int i = tid; i < 32 * 132; i += 128) ah_sh[i] = 0.f;
        } else {
            const float* src = g_ahst[dir][p];
            uint32_t dbase = cvta_s(ah_sh);
            for (int i = tid; i < (BB * AA) / 4; i += 128) {
                int el = i * 4;
                int bb = el >> 7, k = el & 127;
                cp16(dbase + (uint32_t)((bb * 132 + k) * 4), src + el);
            }
            cp_commit();
            cp_wait0();
        }
        __syncthreads();

        const int rowoff = ((b << 8) + t) * NAG + c0 + hc;
        float acc0 = axg[rowoff];
        float acc1 = axg[rowoff + 128];
        float acc2 = axg[rowoff + 256];
        float acc3 = axg[rowoff + 384];

        const float* hp = &ah_sh[b * 132];
        const float* w0 = &aW2[(0 + hc) * 132];
        const float* w1 = &aW2[(4 + hc) * 132];
        const float* w2 = &aW2[(8 + hc) * 132];
        const float* w3 = &aW2[(12 + hc) * 132];
#pragma unroll 8
        for (int k = 0; k < 128; k += 4) {
            float4 h4 = *(const float4*)(hp + k);
            float4 a4 = *(const float4*)(w0 + k);
            float4 b4 = *(const float4*)(w1 + k);
            float4 c4 = *(const float4*)(w2 + k);
            float4 d4 = *(const float4*)(w3 + k);
            acc0 += h4.x * a4.x + h4.y * a4.y + h4.z * a4.z + h4.w * a4.w;
            acc1 += h4.x * b4.x + h4.y * b4.y + h4.z * b4.z + h4.w * b4.w;
            acc2 += h4.x * c4.x + h4.y * c4.y + h4.z * c4.z + h4.w * c4.w;
            acc3 += h4.x * d4.x + h4.y * d4.y + h4.z * d4.z + h4.w * d4.w;
        }

        float ig = sigm(acc0), fg = sigm(acc1), og = sigm(acc3);
        acst = fg * acst + ig * tanhf(acc2);
        float ahv = og * tanhf(acst);

        const int ci = c0 + hc;
        __stcg(&g_ahst[dir][1 - p][(b << 7) + ci], ahv);
        bf16 hh = __float2bfloat16_rn(ahv);
        g_ahT_hi[dir][t][(b << 7) + ci] = hh;
        g_ahT_lo[dir][t][(b << 7) + ci] = __float2bfloat16_rn(ahv - __bfloat162float(hh));

        __syncthreads();
        if (tid == 0) st_release_gpu(&g_aflag[dir][j][0], (unsigned)(t + 1));
    }
}

// ---------------------------------------------------------------------------
// Main scan — R9 phase structure, with FOUR independent MMA accumulators to
// break the 120-MMA RAW chain (reduced at the end of each step).
// ---------------------------------------------------------------------------
#define WSTRIDE 520
#define ZSTRIDE 136
#define MS_SMEM ((4 * 32 * WSTRIDE) * 2 + (4 * 32 * ZSTRIDE) * 2 + 32 * 36 * 4)

__global__ void __launch_bounds__(256, 1) mscan_mma(
    const float* __restrict__ Wh_f, const float* __restrict__ Wh_b,
    const float* __restrict__ Wz_f, const float* __restrict__ Wz_b,
    float* __restrict__ out)
{
    extern __shared__ __align__(16) char smraw[];
    bf16* Whi_s = (bf16*)smraw;                   // [32][520]
    bf16* Wlo_s = Whi_s + 32 * WSTRIDE;
    bf16* Hhi_s = Wlo_s + 32 * WSTRIDE;           // [32][520]
    bf16* Hlo_s = Hhi_s + 32 * WSTRIDE;
    bf16* Zhi_s = Hlo_s + 32 * WSTRIDE;           // [32][136] Wz slice, [c][k]
    bf16* Zlo_s = Zhi_s + 32 * ZSTRIDE;
    bf16* Ehi_s = Zlo_s + 32 * ZSTRIDE;           // [32][136] ah_t, [b][k]
    bf16* Elo_s = Ehi_s + 32 * ZSTRIDE;
    float* gbuf = (float*)(Elo_s + 32 * ZSTRIDE); // [32][36]

    const int bid = blockIdx.x;
    const int dir = bid >> 6;
    const int j   = bid & 63;
    const int hc0 = j * 8;
    const float* Wh = dir ? Wh_b : Wh_f;
    const float* Wz = dir ? Wz_b : Wz_f;
    const float* xg = g_xg[dir];

    const int tid  = threadIdx.x;
    const int w    = tid >> 5, lane = tid & 31;
    const int mh   = w & 1, g = w >> 1;

    for (int i = tid; i < 32 * 512; i += 256) {
        int c = i & 31, k = i >> 5;
        float wv = Wh[(size_t)k * NG + ((c >> 3) << 9) + hc0 + (c & 7)];
        bf16 h = __float2bfloat16_rn(wv);
        Whi_s[c * WSTRIDE + k] = h;
        Wlo_s[c * WSTRIDE + k] = __float2bfloat16_rn(wv - __bfloat162float(h));
    }
    for (int i = tid; i < 32 * 128; i += 256) {
        int c = i & 31, k = i >> 5;
        float wv = Wz[(size_t)k * NG + ((c >> 3) << 9) + hc0 + (c & 7)];
        bf16 h = __float2bfloat16_rn(wv);
        Zhi_s[c * ZSTRIDE + k] = h;
        Zlo_s[c * ZSTRIDE + k] = __float2bfloat16_rn(wv - __bfloat162float(h));
    }
    __syncthreads();

    const uint32_t aH = cvta_s(Hhi_s) + (uint32_t)(((mh * 16 + (lane & 15)) * WSTRIDE + ((lane >> 4) << 3)) * 2);
    const uint32_t aL = cvta_s(Hlo_s) + (uint32_t)(((mh * 16 + (lane & 15)) * WSTRIDE + ((lane >> 4) << 3)) * 2);
    const uint32_t bH = cvta_s(Whi_s) + (uint32_t)(((g * 8 + (lane & 7)) * WSTRIDE + (lane & 8)) * 2);
    const uint32_t bL = cvta_s(Wlo_s) + (uint32_t)(((g * 8 + (lane & 7)) * WSTRIDE + (lane & 8)) * 2);
    const uint32_t aEH = cvta_s(Ehi_s) + (uint32_t)(((mh * 16 + (lane & 15)) * ZSTRIDE + ((lane >> 4) << 3)) * 2);
    const uint32_t aEL = cvta_s(Elo_s) + (uint32_t)(((mh * 16 + (lane & 15)) * ZSTRIDE + ((lane >> 4) << 3)) * 2);
    const uint32_t bZH = cvta_s(Zhi_s) + (uint32_t)(((g * 8 + (lane & 7)) * ZSTRIDE + (lane & 8)) * 2);
    const uint32_t bZL = cvta_s(Zlo_s) + (uint32_t)(((g * 8 + (lane & 7)) * ZSTRIDE + (lane & 8)) * 2);

    const uint32_t eHiBase = cvta_s(Ehi_s);
    const uint32_t eLoBase = cvta_s(Elo_s);
    const uint32_t hHiBase = cvta_s(Hhi_s);
    const uint32_t hLoBase = cvta_s(Hlo_s);

    uint32_t zbh[8][2], zbl[8][2];
#pragma unroll
    for (int c = 0; c < 8; c++) {
        ldsm_x2(zbh[c][0], zbh[c][1], bZH + c * 32);
        ldsm_x2(zbl[c][0], zbl[c][1], bZL + c * 32);
    }

    const int b  = tid >> 3;
    const int hc = tid & 7;
    float cst = 0.f;

    for (int t = 0; t < TT; t++) {
        const int p = t & 1;

        // --- Phase A: ascan-dependent work (peers get time to arrive) ------
        if (tid < 32) poll_flag(&g_aflag[dir][tid][0], (unsigned)(t + 1));
        __syncthreads();
        {
            const bf16* eh = g_ahT_hi[dir][t];
            const bf16* el = g_ahT_lo[dir][t];
            for (int i = tid; i < 512; i += 256) {
                int e = i << 3;
                int bb = e >> 7, k = e & 127;
                uint32_t off = (uint32_t)((bb * ZSTRIDE + k) * 2);
                cp16(eHiBase + off, eh + e);
                cp16(eLoBase + off, el + e);
            }
            cp_commit();
            cp_wait0();
        }
        __syncthreads();

        // FOUR independent accumulators (RAW-chain break); reduced after MMAs
        float ac0[4] = {0.f, 0.f, 0.f, 0.f};
        float ac1[4] = {0.f, 0.f, 0.f, 0.f};
        float ac2[4] = {0.f, 0.f, 0.f, 0.f};
        float ac3[4] = {0.f, 0.f, 0.f, 0.f};
        float* accs[4] = {ac0, ac1, ac2, ac3};

#pragma unroll
        for (int c = 0; c < 8; c++) {
            uint32_t a0, a1, a2, a3, l0, l1, l2, l3;
            ldsm_x4(a0, a1, a2, a3, aEH + c * 32);
            ldsm_x4(l0, l1, l2, l3, aEL + c * 32);
            // 3 MMAs of one chunk spread across 3 different accumulators
            mma_bf16(accs[c & 3],       a0, a1, a2, a3, zbh[c][0], zbh[c][1]);
            mma_bf16(accs[(c + 1) & 3], a0, a1, a2, a3, zbl[c][0], zbl[c][1]);
            mma_bf16(accs[(c + 2) & 3], l0, l1, l2, l3, zbh[c][0], zbh[c][1]);
        }

        const float* xr = xg + (size_t)((b << 8) + t) * NG + hc0 + hc;
        float x0 = xr[0], x1 = xr[512], x2 = xr[1024], x3 = xr[1536];

        // --- Phase B: peer-dependent work ---------------------------------
        if (t > 0 && tid < 64) poll_flag(&g_mflag[dir][tid][0], (unsigned)t);
        __syncthreads();

        if (t == 0) {
            uint4 z = make_uint4(0, 0, 0, 0);
            for (int i = tid; i < (32 * WSTRIDE) / 8; i += 256) {
                ((uint4*)Hhi_s)[i] = z;
                ((uint4*)Hlo_s)[i] = z;
            }
        } else {
            const bf16* sh = g_hsth[dir][p];
            const bf16* sl = g_hstl[dir][p];
            for (int i = tid; i < 2048; i += 256) {
                int e = i << 3;
                int bb = e >> 9, k = e & 511;
                uint32_t off = (uint32_t)((bb * WSTRIDE + k) * 2);
                cp16(hHiBase + off, sh + e);
                cp16(hLoBase + off, sl + e);
            }
            cp_commit();
            cp_wait0();
        }
        __syncthreads();

#pragma unroll 4
        for (int k0 = 0; k0 < 512; k0 += 16) {
            const int kc = k0 >> 4;
            uint32_t ah0, ah1, ah2, ah3, al0, al1, al2, al3, bh0, bh1, bl0, bl1;
            ldsm_x4(ah0, ah1, ah2, ah3, aH + k0 * 2);
            ldsm_x4(al0, al1, al2, al3, aL + k0 * 2);
            ldsm_x2(bh0, bh1, bH + k0 * 2);
            ldsm_x2(bl0, bl1, bL + k0 * 2);
            mma_bf16(accs[kc & 3],       ah0, ah1, ah2, ah3, bh0, bh1);
            mma_bf16(accs[(kc + 1) & 3], ah0, ah1, ah2, ah3, bl0, bl1);
            mma_bf16(accs[(kc + 2) & 3], al0, al1, al2, al3, bh0, bh1);
        }

        // reduce accumulators and scatter to gate buffer
        float c4[4];
#pragma unroll
        for (int i = 0; i < 4; i++)
            c4[i] = (ac0[i] + ac1[i]) + (ac2[i] + ac3[i]);
        {
            int m = mh * 16 + (lane >> 2);
            int nc = g * 8 + ((lane & 3) << 1);
            gbuf[m * 36 + nc]     = c4[0];
            gbuf[m * 36 + nc + 1] = c4[1];
            gbuf[(m + 8) * 36 + nc]     = c4[2];
            gbuf[(m + 8) * 36 + nc + 1] = c4[3];
        }
        __syncthreads();

        float hv;
        {
            float gi = gbuf[b * 36 + hc]      + x0;
            float gf = gbuf[b * 36 + 8 + hc]  + x1;
            float gu = gbuf[b * 36 + 16 + hc] + x2;
            float go = gbuf[b * 36 + 24 + hc] + x3;
            cst = sigm(gf) * cst + sigm(gi) * tanhf(gu);
            hv = sigm(go) * tanhf(cst);

            bf16 hh = __float2bfloat16_rn(hv);
            bf16 hl = __float2bfloat16_rn(hv - __bfloat162float(hh));
            int hidx = (b << 9) + hc0 + hc;
            __stcg(&g_hsth[dir][1 - p][hidx], hh);
            __stcg(&g_hstl[dir][1 - p][hidx], hl);
        }
        __syncthreads();
        if (tid == 0) st_release_gpu(&g_mflag[dir][j][0], (unsigned)(t + 1));

        __stcg(&out[(size_t)((b << 8) + t) * 1024 + (dir << 9) + hc0 + hc], hv);
    }
}

// ---------------------------------------------------------------------------
static cudaStream_t s_side = nullptr;
static cudaEvent_t  s_evA  = nullptr;
static cudaEvent_t  s_evB  = nullptr;

extern "C" void kernel_launch(void* const* d_in, const int* in_sizes, int n_in,
                              void* d_out, int out_size)
{
    const float* x     = (const float*)d_in[0];
    const float* Wx_f  = (const float*)d_in[1];
    const float* Wh_f  = (const float*)d_in[2];
    const float* b_f   = (const float*)d_in[3];
    const float* aWx_f = (const float*)d_in[4];
    const float* aWh_f = (const float*)d_in[5];
    const float* ab_f  = (const float*)d_in[6];
    const float* Wz_f  = (const float*)d_in[7];
    const float* Wx_b  = (const float*)d_in[8];
    const float* Wh_b  = (const float*)d_in[9];
    const float* b_b   = (const float*)d_in[10];
    const float* aWx_b = (const float*)d_in[11];
    const float* aWh_b = (const float*)d_in[12];
    const float* ab_b  = (const float*)d_in[13];
    const float* Wz_b  = (const float*)d_in[14];
    float* out = (float*)d_out;

    if (!s_side) {
        cudaStreamCreateWithFlags(&s_side, cudaStreamNonBlocking);
        cudaEventCreateWithFlags(&s_evA, cudaEventDisableTiming);
        cudaEventCreateWithFlags(&s_evB, cudaEventDisableTiming);
        cudaFuncSetAttribute(mscan_mma, cudaFuncAttributeMaxDynamicSharedMemorySize, MS_SMEM);
    }

    // [1] prep: flag reset + all bf16 splits
    prep<<<1664, 1024>>>(x, Wx_f, Wx_b, aWx_f, aWx_b);

    // [2-3] adaptive x-projections
    gemm_mma<<<dim3(NAG / 128, MROWS / 128), 256>>>(2, ab_f, 2, NAG, DD);
    gemm_mma<<<dim3(NAG / 128, MROWS / 128), 256>>>(3, ab_b, 3, NAG, DD);
    cudaEventRecord(s_evA, 0);

    // [4-5] main x-projections
    gemm_mma<<<dim3(NG / 128, MROWS / 128), 256>>>(0, b_f, 0, NG, DD);
    gemm_mma<<<dim3(NG / 128, MROWS / 128), 256>>>(1, b_b, 1, NG, DD);

    // [6] main scan
    mscan_mma<<<128, 256, MS_SMEM>>>(Wh_f, Wh_b, Wz_f, Wz_b, out);

    // [7] adaptive scan on the side stream (overlaps xg GEMMs + mscan)
    cudaStreamWaitEvent(s_side, s_evA, 0);
    ascan<<<64, 128, 0, s_side>>>(aWh_f, aWh_b);
    cudaEventRecord(s_evB, s_side);

    // join the side branch
    cudaStreamWaitEvent(0, s_evB, 0);
}

// round 15
// speedup vs baseline: 1.4125x; 1.2312x over previous
#include <cuda_runtime.h>
#include <cuda_bf16.h>
#include <cstdint>
#include <math.h>

// ---------------------------------------------------------------------------
// Problem constants
// ---------------------------------------------------------------------------
#define BB   32
#define TT   256
#define DD   512
#define HH   512
#define AA   128
#define MROWS 8192      // B*T
#define NG    2048      // 4H
#define NAG   512       // 4A

typedef __nv_bfloat16 bf16;

// ---------------------------------------------------------------------------
// Static device workspace
// ---------------------------------------------------------------------------
__device__ float g_xg [2][MROWS * NG];    // per dir: x@Wx + b. row = b*T+t
__device__ float g_axg[2][MROWS * NAG];   // per dir: x@aWx + ab. row = b*T+t
__device__ float g_ahst[2][2][BB * AA];   // double-buffered adaptive hidden state
__device__ bf16  g_hsth[2][2][BB * HH];   // double-buffered main hidden (hi)
__device__ bf16  g_hstl[2][2][BB * HH];   // double-buffered main hidden (lo)

// Epoch flags: one 128B-padded slot per CTA
__device__ unsigned g_mflag[2][64][32];   // mscan CTAs
__device__ unsigned g_aflag[2][16][32];   // ascan CTAs (now 16/dir)

// bf16 hi/lo splits
__device__ bf16 g_Xhi [MROWS * DD],  g_Xlo [MROWS * DD];
__device__ bf16 g_Wxhi[2][DD * NG],  g_Wxlo[2][DD * NG];
__device__ bf16 g_aWxhi[2][DD * NAG], g_aWxlo[2][DD * NAG];

// t-major adaptive hidden stream for mscan consumption: [dir][t][b*128+c]
__device__ bf16 g_ahT_hi[2][TT][BB * AA];
__device__ bf16 g_ahT_lo[2][TT][BB * AA];

__device__ __forceinline__ float sigm(float x) { return 1.f / (1.f + expf(-x)); }

// --- release/acquire primitives -------------------------------------------
__device__ __forceinline__ void st_release_gpu(unsigned* p, unsigned v) {
    asm volatile("st.release.gpu.global.u32 [%0], %1;" :: "l"(p), "r"(v));
}
__device__ __forceinline__ unsigned ld_acquire_gpu(const unsigned* p) {
    unsigned v;
    asm volatile("ld.acquire.gpu.global.u32 %0, [%1];" : "=r"(v) : "l"(p));
    return v;
}
__device__ __forceinline__ void poll_flag(const unsigned* p, unsigned tgt) {
    int s = 0;
    while (ld_acquire_gpu(p) < tgt) {
        if (++s > 16) __nanosleep(40);
    }
}

// --- cp.async (16B, L2-direct) --------------------------------------------
__device__ __forceinline__ void cp16(uint32_t dst, const void* src) {
    asm volatile("cp.async.cg.shared.global [%0], [%1], 16;" :: "r"(dst), "l"(src));
}
__device__ __forceinline__ void cp_commit() {
    asm volatile("cp.async.commit_group;");
}
__device__ __forceinline__ void cp_wait0() {
    asm volatile("cp.async.wait_group 0;" ::: "memory");
}

// ---------------------------------------------------------------------------
// mma.sync helpers (bf16, m16n8k16, fp32 accumulate)
// ---------------------------------------------------------------------------
__device__ __forceinline__ uint32_t cvta_s(const void* p) {
    return (uint32_t)__cvta_generic_to_shared(p);
}
__device__ __forceinline__ void ldsm_x4(uint32_t& r0, uint32_t& r1, uint32_t& r2, uint32_t& r3, uint32_t a) {
    asm volatile("ldmatrix.sync.aligned.m8n8.x4.shared.b16 {%0,%1,%2,%3}, [%4];"
                 : "=r"(r0), "=r"(r1), "=r"(r2), "=r"(r3) : "r"(a));
}
__device__ __forceinline__ void ldsm_x2(uint32_t& r0, uint32_t& r1, uint32_t a) {
    asm volatile("ldmatrix.sync.aligned.m8n8.x2.shared.b16 {%0,%1}, [%2];"
                 : "=r"(r0), "=r"(r1) : "r"(a));
}
__device__ __forceinline__ void ldsm_x2t(uint32_t& r0, uint32_t& r1, uint32_t a) {
    asm volatile("ldmatrix.sync.aligned.m8n8.x2.trans.shared.b16 {%0,%1}, [%2];"
                 : "=r"(r0), "=r"(r1) : "r"(a));
}
__device__ __forceinline__ void mma_bf16(float* c, uint32_t a0, uint32_t a1, uint32_t a2, uint32_t a3,
                                         uint32_t b0, uint32_t b1) {
    asm volatile(
        "mma.sync.aligned.m16n8k16.row.col.f32.bf16.bf16.f32 "
        "{%0,%1,%2,%3}, {%4,%5,%6,%7}, {%8,%9}, {%0,%1,%2,%3};"
        : "+f"(c[0]), "+f"(c[1]), "+f"(c[2]), "+f"(c[3])
        : "r"(a0), "r"(a1), "r"(a2), "r"(a3), "r"(b0), "r"(b1));
}

// ---------------------------------------------------------------------------
// prep: ONE kernel — flag reset + ALL fp32->bf16 hi/lo splits
// ---------------------------------------------------------------------------
#define N_X4   (MROWS * DD / 4)
#define N_WX4  (DD * NG / 4)
#define N_AWX4 (DD * NAG / 4)
#define N_TOT4 (N_X4 + 2 * N_WX4 + 2 * N_AWX4)

__device__ __forceinline__ void split4(const float4* s4, bf16* hi, bf16* lo, int i) {
    float4 v = s4[i];
    bf16 hx = __float2bfloat16_rn(v.x);
    bf16 hy = __float2bfloat16_rn(v.y);
    bf16 hz = __float2bfloat16_rn(v.z);
    bf16 hw = __float2bfloat16_rn(v.w);
    __nv_bfloat162 hp0, hp1, lp0, lp1;
    hp0.x = hx; hp0.y = hy; hp1.x = hz; hp1.y = hw;
    lp0.x = __float2bfloat16_rn(v.x - __bfloat162float(hx));
    lp0.y = __float2bfloat16_rn(v.y - __bfloat162float(hy));
    lp1.x = __float2bfloat16_rn(v.z - __bfloat162float(hz));
    lp1.y = __float2bfloat16_rn(v.w - __bfloat162float(hw));
    ((uint2*)hi)[i] = make_uint2(*(uint32_t*)&hp0, *(uint32_t*)&hp1);
    ((uint2*)lo)[i] = make_uint2(*(uint32_t*)&lp0, *(uint32_t*)&lp1);
}

__global__ void prep(const float* __restrict__ x,
                     const float* __restrict__ Wx_f, const float* __restrict__ Wx_b,
                     const float* __restrict__ aWx_f, const float* __restrict__ aWx_b)
{
    int gid = blockIdx.x * blockDim.x + threadIdx.x;
    if (gid < 2 * 64 * 32) ((unsigned*)g_mflag)[gid] = 0u;
    if (gid < 2 * 16 * 32) ((unsigned*)g_aflag)[gid] = 0u;

    for (int i = gid; i < N_TOT4; i += gridDim.x * blockDim.x) {
        int r = i;
        if (r < N_X4) { split4((const float4*)x, g_Xhi, g_Xlo, r); continue; }
        r -= N_X4;
        if (r < N_WX4) { split4((const float4*)Wx_f, g_Wxhi[0], g_Wxlo[0], r); continue; }
        r -= N_WX4;
        if (r < N_WX4) { split4((const float4*)Wx_b, g_Wxhi[1], g_Wxlo[1], r); continue; }
        r -= N_WX4;
        if (r < N_AWX4) { split4((const float4*)aWx_f, g_aWxhi[0], g_aWxlo[0], r); continue; }
        r -= N_AWX4;
        split4((const float4*)aWx_b, g_aWxhi[1], g_aWxlo[1], r);
    }
}

// ---------------------------------------------------------------------------
// bf16-split GEMM — exact R9/R13 version (the 2750us-run variant). FROZEN.
// ---------------------------------------------------------------------------
__global__ void __launch_bounds__(256, 2) gemm_mma(
    int bsel, const float* __restrict__ bias, int csel, int N, int K)
{
    const bf16 *Ahi = g_Xhi, *Alo = g_Xlo;
    const bf16 *Bhi, *Blo;
    float* C;
    switch (bsel) {
        case 0:  Bhi = g_Wxhi[0];  Blo = g_Wxlo[0];  break;
        case 1:  Bhi = g_Wxhi[1];  Blo = g_Wxlo[1];  break;
        case 2:  Bhi = g_aWxhi[0]; Blo = g_aWxlo[0]; break;
        default: Bhi = g_aWxhi[1]; Blo = g_aWxlo[1]; break;
    }
    switch (csel) {
        case 0:  C = g_xg[0];  break;
        case 1:  C = g_xg[1];  break;
        case 2:  C = g_axg[0]; break;
        default: C = g_axg[1]; break;
    }

    __shared__ __align__(16) bf16 sAh[128 * 24], sAl[128 * 24];
    __shared__ __align__(16) bf16 sBh[16 * 136], sBl[16 * 136];

    const int tid  = threadIdx.x;
    const int w    = tid >> 5, lane = tid & 31;
    const int wm   = w & 1,    wn   = w >> 1;
    const int bm   = blockIdx.y * 128;
    const int bn   = blockIdx.x * 128;

    const int arow = tid >> 1, ahalf = tid & 1;
    const int brow = tid >> 4, bseg  = tid & 15;

    float acc[4][4][4];
#pragma unroll
    for (int i = 0; i < 4; i++)
#pragma unroll
        for (int j = 0; j < 4; j++) {
            acc[i][j][0] = 0.f; acc[i][j][1] = 0.f; acc[i][j][2] = 0.f; acc[i][j][3] = 0.f;
        }

    const uint32_t aBaseH = cvta_s(sAh) + (uint32_t)(((wm * 64 + (lane & 15)) * 24 + ((lane >> 4) << 3)) * 2);
    const uint32_t aBaseL = cvta_s(sAl) + (uint32_t)(((wm * 64 + (lane & 15)) * 24 + ((lane >> 4) << 3)) * 2);
    const uint32_t bBaseH = cvta_s(sBh) + (uint32_t)((((lane & 15)) * 136 + wn * 32) * 2);
    const uint32_t bBaseL = cvta_s(sBl) + (uint32_t)((((lane & 15)) * 136 + wn * 32) * 2);

#pragma unroll 1
    for (int k0 = 0; k0 < K; k0 += 16) {
        *(uint4*)&sAh[arow * 24 + ahalf * 8] = *(const uint4*)&Ahi[(size_t)(bm + arow) * K + k0 + ahalf * 8];
        *(uint4*)&sAl[arow * 24 + ahalf * 8] = *(const uint4*)&Alo[(size_t)(bm + arow) * K + k0 + ahalf * 8];
        *(uint4*)&sBh[brow * 136 + bseg * 8] = *(const uint4*)&Bhi[(size_t)(k0 + brow) * N + bn + bseg * 8];
        *(uint4*)&sBl[brow * 136 + bseg * 8] = *(const uint4*)&Blo[(size_t)(k0 + brow) * N + bn + bseg * 8];
        __syncthreads();

        uint32_t bh[4][2], bl[4][2];
#pragma unroll
        for (int nt = 0; nt < 4; nt++) {
            ldsm_x2t(bh[nt][0], bh[nt][1], bBaseH + nt * 16);
            ldsm_x2t(bl[nt][0], bl[nt][1], bBaseL + nt * 16);
        }
#pragma unroll
        for (int mt = 0; mt < 4; mt++) {
            uint32_t a0, a1, a2, a3, l0, l1, l2, l3;
            ldsm_x4(a0, a1, a2, a3, aBaseH + mt * 768);
            ldsm_x4(l0, l1, l2, l3, aBaseL + mt * 768);
#pragma unroll
            for (int nt = 0; nt < 4; nt++) {
                mma_bf16(acc[mt][nt], a0, a1, a2, a3, bh[nt][0], bh[nt][1]);
                mma_bf16(acc[mt][nt], a0, a1, a2, a3, bl[nt][0], bl[nt][1]);
                mma_bf16(acc[mt][nt], l0, l1, l2, l3, bh[nt][0], bh[nt][1]);
            }
        }
        __syncthreads();
    }

#pragma unroll
    for (int mt = 0; mt < 4; mt++)
#pragma unroll
        for (int nt = 0; nt < 4; nt++) {
            int m = bm + wm * 64 + mt * 16 + (lane >> 2);
            int n = bn + wn * 32 + nt * 8 + ((lane & 3) << 1);
            float b0 = bias ? bias[n] : 0.f;
            float b1 = bias ? bias[n + 1] : 0.f;
            *(float2*)&C[(size_t)m * N + n] = make_float2(acc[mt][nt][0] + b0, acc[mt][nt][1] + b1);
            *(float2*)&C[(size_t)(m + 8) * N + n] = make_float2(acc[mt][nt][2] + b0, acc[mt][nt][3] + b1);
        }
}

// ---------------------------------------------------------------------------
// Adaptive scan — 32 CTAs (16/dir) x 256 threads, 8 cols/CTA/gate.
// Dynamic smem padded to 72KB so ascan CANNOT co-reside with mscan (168.5KB):
// the 20 mscan-free SMs hold 3 ascan CTAs each. Zero interference with mscan.
// ---------------------------------------------------------------------------
#define ASCAN_SMEM 73728   // 72KB (used: 2 * 32*132 floats = 33KB)

__global__ void __launch_bounds__(256, 1) ascan(
    const float* __restrict__ aWh_f, const float* __restrict__ aWh_b)
{
    extern __shared__ float asmem[];
    float* aW2   = asmem;              // [32][132]  col c = g*8 + hc
    float* ah_sh = asmem + 32 * 132;   // [32][132]  [b][k]

    const int bid = blockIdx.x;        // 0..31
    const int dir = bid >> 4;
    const int j   = bid & 15;
    const int c0  = j * 8;
    const float* aWh = dir ? aWh_b : aWh_f;
    const float* axg = g_axg[dir];

    const int tid = threadIdx.x;
    for (int i = tid; i < 32 * 128; i += 256) {
        int k = i >> 5, c = i & 31;
        int g = c >> 3, hc = c & 7;
        aW2[c * 132 + k] = aWh[k * NAG + (g << 7) + c0 + hc];
    }

    const int b  = tid >> 3;           // 0..31
    const int hc = tid & 7;            // 0..7
    float acst = 0.f;

    for (int t = 0; t < TT; t++) {
        const int p = t & 1;
        if (t > 0 && tid < 16) poll_flag(&g_aflag[dir][tid][0], (unsigned)t);
        __syncthreads();

        if (t == 0) {
            for (int i = tid; i < 32 * 132; i += 256) ah_sh[i] = 0.f;
        } else {
            const float* src = g_ahst[dir][p];
            uint32_t dbase = cvta_s(ah_sh);
            for (int i = tid; i < (BB * AA) / 4; i += 256) {
                int el = i * 4;
                int bb = el >> 7, k = el & 127;
                cp16(dbase + (uint32_t)((bb * 132 + k) * 4), src + el);
            }
            cp_commit();
            cp_wait0();
        }
        __syncthreads();

        const int rowoff = ((b << 8) + t) * NAG + c0 + hc;
        float acc0 = axg[rowoff];
        float acc1 = axg[rowoff + 128];
        float acc2 = axg[rowoff + 256];
        float acc3 = axg[rowoff + 384];

        const float* hp = &ah_sh[b * 132];
        const float* w0 = &aW2[(0  + hc) * 132];
        const float* w1 = &aW2[(8  + hc) * 132];
        const float* w2 = &aW2[(16 + hc) * 132];
        const float* w3 = &aW2[(24 + hc) * 132];
#pragma unroll 8
        for (int k = 0; k < 128; k += 4) {
            float4 h4 = *(const float4*)(hp + k);
            float4 a4 = *(const float4*)(w0 + k);
            float4 b4 = *(const float4*)(w1 + k);
            float4 c4 = *(const float4*)(w2 + k);
            float4 d4 = *(const float4*)(w3 + k);
            acc0 += h4.x * a4.x + h4.y * a4.y + h4.z * a4.z + h4.w * a4.w;
            acc1 += h4.x * b4.x + h4.y * b4.y + h4.z * b4.z + h4.w * b4.w;
            acc2 += h4.x * c4.x + h4.y * c4.y + h4.z * c4.z + h4.w * c4.w;
            acc3 += h4.x * d4.x + h4.y * d4.y + h4.z * d4.z + h4.w * d4.w;
        }

        float ig = sigm(acc0), fg = sigm(acc1), og = sigm(acc3);
        acst = fg * acst + ig * tanhf(acc2);
        float ahv = og * tanhf(acst);

        const int ci = c0 + hc;
        __stcg(&g_ahst[dir][1 - p][(b << 7) + ci], ahv);
        bf16 hh = __float2bfloat16_rn(ahv);
        g_ahT_hi[dir][t][(b << 7) + ci] = hh;
        g_ahT_lo[dir][t][(b << 7) + ci] = __float2bfloat16_rn(ahv - __bfloat162float(hh));

        __syncthreads();
        if (tid == 0) st_release_gpu(&g_aflag[dir][j][0], (unsigned)(t + 1));
    }
}

// ---------------------------------------------------------------------------
// Main scan — R14 version (best). Only change: polls 16 aflags instead of 32.
// ---------------------------------------------------------------------------
#define WSTRIDE 520
#define ZSTRIDE 136
#define MS_SMEM ((4 * 32 * WSTRIDE) * 2 + (4 * 32 * ZSTRIDE) * 2 + 32 * 36 * 4)

__global__ void __launch_bounds__(256, 1) mscan_mma(
    const float* __restrict__ Wh_f, const float* __restrict__ Wh_b,
    const float* __restrict__ Wz_f, const float* __restrict__ Wz_b,
    float* __restrict__ out)
{
    extern __shared__ __align__(16) char smraw[];
    bf16* Whi_s = (bf16*)smraw;                   // [32][520]
    bf16* Wlo_s = Whi_s + 32 * WSTRIDE;
    bf16* Hhi_s = Wlo_s + 32 * WSTRIDE;           // [32][520]
    bf16* Hlo_s = Hhi_s + 32 * WSTRIDE;
    bf16* Zhi_s = Hlo_s + 32 * WSTRIDE;           // [32][136] Wz slice, [c][k]
    bf16* Zlo_s = Zhi_s + 32 * ZSTRIDE;
    bf16* Ehi_s = Zlo_s + 32 * ZSTRIDE;           // [32][136] ah_t, [b][k]
    bf16* Elo_s = Ehi_s + 32 * ZSTRIDE;
    float* gbuf = (float*)(Elo_s + 32 * ZSTRIDE); // [32][36]

    const int bid = blockIdx.x;
    const int dir = bid >> 6;
    const int j   = bid & 63;
    const int hc0 = j * 8;
    const float* Wh = dir ? Wh_b : Wh_f;
    const float* Wz = dir ? Wz_b : Wz_f;
    const float* xg = g_xg[dir];

    const int tid  = threadIdx.x;
    const int w    = tid >> 5, lane = tid & 31;
    const int mh   = w & 1, g = w >> 1;

    for (int i = tid; i < 32 * 512; i += 256) {
        int c = i & 31, k = i >> 5;
        float wv = Wh[(size_t)k * NG + ((c >> 3) << 9) + hc0 + (c & 7)];
        bf16 h = __float2bfloat16_rn(wv);
        Whi_s[c * WSTRIDE + k] = h;
        Wlo_s[c * WSTRIDE + k] = __float2bfloat16_rn(wv - __bfloat162float(h));
    }
    for (int i = tid; i < 32 * 128; i += 256) {
        int c = i & 31, k = i >> 5;
        float wv = Wz[(size_t)k * NG + ((c >> 3) << 9) + hc0 + (c & 7)];
        bf16 h = __float2bfloat16_rn(wv);
        Zhi_s[c * ZSTRIDE + k] = h;
        Zlo_s[c * ZSTRIDE + k] = __float2bfloat16_rn(wv - __bfloat162float(h));
    }
    __syncthreads();

    const uint32_t aH = cvta_s(Hhi_s) + (uint32_t)(((mh * 16 + (lane & 15)) * WSTRIDE + ((lane >> 4) << 3)) * 2);
    const uint32_t aL = cvta_s(Hlo_s) + (uint32_t)(((mh * 16 + (lane & 15)) * WSTRIDE + ((lane >> 4) << 3)) * 2);
    const uint32_t bH = cvta_s(Whi_s) + (uint32_t)(((g * 8 + (lane & 7)) * WSTRIDE + (lane & 8)) * 2);
    const uint32_t bL = cvta_s(Wlo_s) + (uint32_t)(((g * 8 + (lane & 7)) * WSTRIDE + (lane & 8)) * 2);
    const uint32_t aEH = cvta_s(Ehi_s) + (uint32_t)(((mh * 16 + (lane & 15)) * ZSTRIDE + ((lane >> 4) << 3)) * 2);
    const uint32_t aEL = cvta_s(Elo_s) + (uint32_t)(((mh * 16 + (lane & 15)) * ZSTRIDE + ((lane >> 4) << 3)) * 2);
    const uint32_t bZH = cvta_s(Zhi_s) + (uint32_t)(((g * 8 + (lane & 7)) * ZSTRIDE + (lane & 8)) * 2);
    const uint32_t bZL = cvta_s(Zlo_s) + (uint32_t)(((g * 8 + (lane & 7)) * ZSTRIDE + (lane & 8)) * 2);

    const uint32_t eHiBase = cvta_s(Ehi_s);
    const uint32_t eLoBase = cvta_s(Elo_s);
    const uint32_t hHiBase = cvta_s(Hhi_s);
    const uint32_t hLoBase = cvta_s(Hlo_s);

    uint32_t zbh[8][2], zbl[8][2];
#pragma unroll
    for (int c = 0; c < 8; c++) {
        ldsm_x2(zbh[c][0], zbh[c][1], bZH + c * 32);
        ldsm_x2(zbl[c][0], zbl[c][1], bZL + c * 32);
    }

    const int b  = tid >> 3;
    const int hc = tid & 7;
    float cst = 0.f;

    for (int t = 0; t < TT; t++) {
        const int p = t & 1;

        // --- Phase A: ascan-dependent work (peers get time to arrive) ------
        if (tid < 16) poll_flag(&g_aflag[dir][tid][0], (unsigned)(t + 1));
        __syncthreads();
        {
            const bf16* eh = g_ahT_hi[dir][t];
            const bf16* el = g_ahT_lo[dir][t];
            for (int i = tid; i < 512; i += 256) {
                int e = i << 3;
                int bb = e >> 7, k = e & 127;
                uint32_t off = (uint32_t)((bb * ZSTRIDE + k) * 2);
                cp16(eHiBase + off, eh + e);
                cp16(eLoBase + off, el + e);
            }
            cp_commit();
            cp_wait0();
        }
        __syncthreads();

        float ac0[4] = {0.f, 0.f, 0.f, 0.f};
        float ac1[4] = {0.f, 0.f, 0.f, 0.f};
        float ac2[4] = {0.f, 0.f, 0.f, 0.f};
        float ac3[4] = {0.f, 0.f, 0.f, 0.f};
        float* accs[4] = {ac0, ac1, ac2, ac3};

#pragma unroll
        for (int c = 0; c < 8; c++) {
            uint32_t a0, a1, a2, a3, l0, l1, l2, l3;
            ldsm_x4(a0, a1, a2, a3, aEH + c * 32);
            ldsm_x4(l0, l1, l2, l3, aEL + c * 32);
            mma_bf16(accs[c & 3],       a0, a1, a2, a3, zbh[c][0], zbh[c][1]);
            mma_bf16(accs[(c + 1) & 3], a0, a1, a2, a3, zbl[c][0], zbl[c][1]);
            mma_bf16(accs[(c + 2) & 3], l0, l1, l2, l3, zbh[c][0], zbh[c][1]);
        }

        const float* xr = xg + (size_t)((b << 8) + t) * NG + hc0 + hc;
        float x0 = xr[0], x1 = xr[512], x2 = xr[1024], x3 = xr[1536];

        // --- Phase B: peer-dependent work ---------------------------------
        if (t > 0 && tid < 64) poll_flag(&g_mflag[dir][tid][0], (unsigned)t);
        __syncthreads();

        if (t == 0) {
            uint4 z = make_uint4(0, 0, 0, 0);
            for (int i = tid; i < (32 * WSTRIDE) / 8; i += 256) {
                ((uint4*)Hhi_s)[i] = z;
                ((uint4*)Hlo_s)[i] = z;
            }
        } else {
            const bf16* sh = g_hsth[dir][p];
            const bf16* sl = g_hstl[dir][p];
            for (int i = tid; i < 2048; i += 256) {
                int e = i << 3;
                int bb = e >> 9, k = e & 511;
                uint32_t off = (uint32_t)((bb * WSTRIDE + k) * 2);
                cp16(hHiBase + off, sh + e);
                cp16(hLoBase + off, sl + e);
            }
            cp_commit();
            cp_wait0();
        }
        __syncthreads();

#pragma unroll 4
        for (int k0 = 0; k0 < 512; k0 += 16) {
            const int kc = k0 >> 4;
            uint32_t ah0, ah1, ah2, ah3, al0, al1, al2, al3, bh0, bh1, bl0, bl1;
            ldsm_x4(ah0, ah1, ah2, ah3, aH + k0 * 2);
            ldsm_x4(al0, al1, al2, al3, aL + k0 * 2);
            ldsm_x2(bh0, bh1, bH + k0 * 2);
            ldsm_x2(bl0, bl1, bL + k0 * 2);
            mma_bf16(accs[kc & 3],       ah0, ah1, ah2, ah3, bh0, bh1);
            mma_bf16(accs[(kc + 1) & 3], ah0, ah1, ah2, ah3, bl0, bl1);
            mma_bf16(accs[(kc + 2) & 3], al0, al1, al2, al3, bh0, bh1);
        }

        float c4[4];
#pragma unroll
        for (int i = 0; i < 4; i++)
            c4[i] = (ac0[i] + ac1[i]) + (ac2[i] + ac3[i]);
        {
            int m = mh * 16 + (lane >> 2);
            int nc = g * 8 + ((lane & 3) << 1);
            gbuf[m * 36 + nc]     = c4[0];
            gbuf[m * 36 + nc + 1] = c4[1];
            gbuf[(m + 8) * 36 + nc]     = c4[2];
            gbuf[(m + 8) * 36 + nc + 1] = c4[3];
        }
        __syncthreads();

        float hv;
        {
            float gi = gbuf[b * 36 + hc]      + x0;
            float gf = gbuf[b * 36 + 8 + hc]  + x1;
            float gu = gbuf[b * 36 + 16 + hc] + x2;
            float go = gbuf[b * 36 + 24 + hc] + x3;
            cst = sigm(gf) * cst + sigm(gi) * tanhf(gu);
            hv = sigm(go) * tanhf(cst);

            bf16 hh = __float2bfloat16_rn(hv);
            bf16 hl = __float2bfloat16_rn(hv - __bfloat162float(hh));
            int hidx = (b << 9) + hc0 + hc;
            __stcg(&g_hsth[dir][1 - p][hidx], hh);
            __stcg(&g_hstl[dir][1 - p][hidx], hl);
        }
        __syncthreads();
        if (tid == 0) st_release_gpu(&g_mflag[dir][j][0], (unsigned)(t + 1));

        __stcg(&out[(size_t)((b << 8) + t) * 1024 + (dir << 9) + hc0 + hc], hv);
    }
}

// ---------------------------------------------------------------------------
static cudaStream_t s_side = nullptr;
static cudaEvent_t  s_evA  = nullptr;
static cudaEvent_t  s_evB  = nullptr;

extern "C" void kernel_launch(void* const* d_in, const int* in_sizes, int n_in,
                              void* d_out, int out_size)
{
    const float* x     = (const float*)d_in[0];
    const float* Wx_f  = (const float*)d_in[1];
    const float* Wh_f  = (const float*)d_in[2];
    const float* b_f   = (const float*)d_in[3];
    const float* aWx_f = (const float*)d_in[4];
    const float* aWh_f = (const float*)d_in[5];
    const float* ab_f  = (const float*)d_in[6];
    const float* Wz_f  = (const float*)d_in[7];
    const float* Wx_b  = (const float*)d_in[8];
    const float* Wh_b  = (const float*)d_in[9];
    const float* b_b   = (const float*)d_in[10];
    const float* aWx_b = (const float*)d_in[11];
    const float* aWh_b = (const float*)d_in[12];
    const float* ab_b  = (const float*)d_in[13];
    const float* Wz_b  = (const float*)d_in[14];
    float* out = (float*)d_out;

    if (!s_side) {
        cudaStreamCreateWithFlags(&s_side, cudaStreamNonBlocking);
        cudaEventCreateWithFlags(&s_evA, cudaEventDisableTiming);
        cudaEventCreateWithFlags(&s_evB, cudaEventDisableTiming);
        cudaFuncSetAttribute(mscan_mma, cudaFuncAttributeMaxDynamicSharedMemorySize, MS_SMEM);
        cudaFuncSetAttribute(ascan, cudaFuncAttributeMaxDynamicSharedMemorySize, ASCAN_SMEM);
    }

    // [1] prep: flag reset + all bf16 splits
    prep<<<1664, 1024>>>(x, Wx_f, Wx_b, aWx_f, aWx_b);

    // [2-3] adaptive x-projections
    gemm_mma<<<dim3(NAG / 128, MROWS / 128), 256>>>(2, ab_f, 2, NAG, DD);
    gemm_mma<<<dim3(NAG / 128, MROWS / 128), 256>>>(3, ab_b, 3, NAG, DD);
    cudaEventRecord(s_evA, 0);

    // [4-5] main x-projections
    gemm_mma<<<dim3(NG / 128, MROWS / 128), 256>>>(0, b_f, 0, NG, DD);
    gemm_mma<<<dim3(NG / 128, MROWS / 128), 256>>>(1, b_b, 1, NG, DD);

    // [6] main scan
    mscan_mma<<<128, 256, MS_SMEM>>>(Wh_f, Wh_b, Wz_f, Wz_b, out);

    // [7] adaptive scan — 32 CTAs with 72KB smem: forced onto the 20 SMs
    //     that hold no mscan CTA (168.5KB + 72KB > SM smem capacity).
    cudaStreamWaitEvent(s_side, s_evA, 0);
    ascan<<<32, 256, ASCAN_SMEM, s_side>>>(aWh_f, aWh_b);
    cudaEventRecord(s_evB, s_side);

    // join the side branch
    cudaStreamWaitEvent(0, s_evB, 0);
}